// round 6
// baseline (speedup 1.0000x reference)
#include <cuda_runtime.h>

typedef unsigned long long ull;
#define NT 512
#define SCALE 0.17677669529663687f

// ---- shared memory layout (float offsets) ----
#define XS_OFF 0
#define XS_STR 68              // xs[k=384][t=64 +pad] : 384*68 = 26112
#define WB_OFF 26112           // 9216 floats: qkv chunk [48][192] / wout chunk [16][384]
#define QS_OFF 35328           // qs[2][64][33] = 4224 ; ALIASED by os_t[2][32][66]
#define KS_OFF 39552           // ks_t[2][32][68] = 4352
#define VS_OFF 43904           // vs[2][64][36] = 4608
#define PS_OFF 48512           // ps[2][64][66] = 8448
#define SMEM_FLOATS 56960      // 227,840 bytes

__device__ __forceinline__ ull pk2(float lo, float hi) {
    ull r; asm("mov.b64 %0,{%1,%2};" : "=l"(r) : "f"(lo), "f"(hi)); return r;
}
__device__ __forceinline__ void upk2(ull v, float &lo, float &hi) {
    asm("mov.b64 {%0,%1},%2;" : "=f"(lo), "=f"(hi) : "l"(v));
}
__device__ __forceinline__ void ffma2(ull &d, ull a, ull b) {
    asm("fma.rn.f32x2 %0,%1,%2,%0;" : "+l"(d) : "l"(a), "l"(b));
}

__global__ void __launch_bounds__(NT, 1)
winattn2(const float* __restrict__ x, const float* __restrict__ wqkv,
         const float* __restrict__ wout, const float* __restrict__ bias,
         float* __restrict__ out)
{
    extern __shared__ float sm[];
    const int tid  = threadIdx.x;
    const int lane = tid & 31;
    const int w    = tid >> 5;

    const int n  = blockIdx.x;
    const int b  = n >> 6;
    const int ih = (n >> 3) & 7;
    const int iw = n & 7;
    const long gbase = (((long)b * 64 + ih * 8) * 64 + iw * 8) * 384;

    // ---- stage x window TRANSPOSED: xs[d][t] ----
#pragma unroll
    for (int i = 0; i < 48; i++) {
        int e = i * NT + tid;                 // 0..24575
        int t = e / 384, d = e - t * 384;
        sm[XS_OFF + d * XS_STR + t] = x[gbase + (((t >> 3) * 64) + (t & 7)) * 384 + d];
    }

    // QKV mapping: warp = (hq, r); 8 tokens x 96 cols (1 head); thread: 8 tok x 3 cols
    const int hq = w >> 3;                    // head-in-pair 0/1
    const int r  = w & 7;
    const int t0 = r * 8;
    const int c3 = lane * 3;

    // attention mapping: 2 heads in parallel across 512 threads
    const int hh   = tid >> 8;
    const int st   = tid & 255;
    const int s_r  = st >> 2;                 // row 0..63
    const int cg   = st & 3;
    const int s_c0 = cg * 16;                 // 16 score cols
    const int a_d0 = cg * 8;                  // 8 AV dims

    // out-proj mapping: warp -> 4 tokens; thread cols = lane + 32*jj
    const int t4 = w * 4;

    ull oa0[12], oa1[12];                     // 48 output floats: (t4,t4+1) and (t4+2,t4+3)
#pragma unroll
    for (int jj = 0; jj < 12; jj++) { oa0[jj] = 0ull; oa1[jj] = 0ull; }

    for (int hp = 0; hp < 6; hp++) {
        // ================= QKV GEMM (2 heads), C[64][192] =================
        ull acc[4][3];
#pragma unroll
        for (int p = 0; p < 4; p++) { acc[p][0] = acc[p][1] = acc[p][2] = 0ull; }

        // preload chunk 0 (48 k-rows x 192 cols)
        float pre[18];
#pragma unroll
        for (int i = 0; i < 18; i++) {
            int e  = i * NT + tid;            // 0..9215
            int kr = e / 192, c = e - kr * 192;
            int h2 = c / 96,  cc = c - h2 * 96;
            int gcol = (cc >> 5) * 384 + (hp * 2 + h2) * 32 + (cc & 31);
            pre[i] = wqkv[(long)kr * 1152 + gcol];
        }

        for (int ch = 0; ch < 8; ch++) {
            __syncthreads();                  // WB free (prior readers done)
#pragma unroll
            for (int i = 0; i < 18; i++) sm[WB_OFF + i * NT + tid] = pre[i];
            if (ch < 7) {
#pragma unroll
                for (int i = 0; i < 18; i++) {
                    int e  = i * NT + tid;
                    int kr = e / 192, c = e - kr * 192;
                    int h2 = c / 96,  cc = c - h2 * 96;
                    int gcol = (cc >> 5) * 384 + (hp * 2 + h2) * 32 + (cc & 31);
                    pre[i] = wqkv[(long)((ch + 1) * 48 + kr) * 1152 + gcol];
                }
            }
            __syncthreads();
            const float* xp = &sm[XS_OFF + (ch * 48) * XS_STR + t0];
            const float* wp = &sm[WB_OFF + hq * 96 + c3];
#pragma unroll 4
            for (int kk = 0; kk < 48; kk++) {
                ulonglong2 u0 = *(const ulonglong2*)(xp + kk * XS_STR);     // tok t0..t0+3
                ulonglong2 u1 = *(const ulonglong2*)(xp + kk * XS_STR + 4); // tok t0+4..t0+7
                float b0 = wp[kk * 192 + 0];
                float b1 = wp[kk * 192 + 1];
                float b2 = wp[kk * 192 + 2];
                ull B0 = pk2(b0, b0), B1 = pk2(b1, b1), B2 = pk2(b2, b2);
                ffma2(acc[0][0], u0.x, B0); ffma2(acc[0][1], u0.x, B1); ffma2(acc[0][2], u0.x, B2);
                ffma2(acc[1][0], u0.y, B0); ffma2(acc[1][1], u0.y, B1); ffma2(acc[1][2], u0.y, B2);
                ffma2(acc[2][0], u1.x, B0); ffma2(acc[2][1], u1.x, B1); ffma2(acc[2][2], u1.x, B2);
                ffma2(acc[3][0], u1.y, B0); ffma2(acc[3][1], u1.y, B1); ffma2(acc[3][2], u1.y, B2);
            }
        }
        __syncthreads();                      // QKV done; prior out-proj os reads long done

        // ---- scatter to q (scaled), k^T, v ----
#pragma unroll
        for (int p = 0; p < 4; p++) {
            int t = t0 + 2 * p;
#pragma unroll
            for (int j = 0; j < 3; j++) {
                int c = c3 + j;
                float f0, f1; upk2(acc[p][j], f0, f1);
                if (c < 32) {
                    sm[QS_OFF + hq * 2112 + t * 33 + c]       = f0 * SCALE;
                    sm[QS_OFF + hq * 2112 + (t + 1) * 33 + c] = f1 * SCALE;
                } else if (c < 64) {
                    *(ull*)&sm[KS_OFF + hq * 2176 + (c - 32) * 68 + t] = acc[p][j];
                } else {
                    sm[VS_OFF + hq * 2304 + t * 36 + (c - 64)]       = f0;
                    sm[VS_OFF + hq * 2304 + (t + 1) * 36 + (c - 64)] = f1;
                }
            }
        }
        __syncthreads();

        // ================= scores + softmax =================
        {
            ull sc[8];
#pragma unroll
            for (int j = 0; j < 8; j++) sc[j] = 0ull;
            const float* qrow  = &sm[QS_OFF + hh * 2112 + s_r * 33];
            const float* kbase = &sm[KS_OFF + hh * 2176 + s_c0];
#pragma unroll 4
            for (int d = 0; d < 32; d++) {
                float qv = qrow[d];
                ull qq = pk2(qv, qv);
                const ulonglong2* kp = (const ulonglong2*)(kbase + d * 68);
                ulonglong2 k0 = kp[0], k1 = kp[1], k2 = kp[2], k3 = kp[3];
                ffma2(sc[0], qq, k0.x); ffma2(sc[1], qq, k0.y);
                ffma2(sc[2], qq, k1.x); ffma2(sc[3], qq, k1.y);
                ffma2(sc[4], qq, k2.x); ffma2(sc[5], qq, k2.y);
                ffma2(sc[6], qq, k3.x); ffma2(sc[7], qq, k3.y);
            }
            float sv[16];
#pragma unroll
            for (int j = 0; j < 8; j++) upk2(sc[j], sv[2 * j], sv[2 * j + 1]);
            float m = sv[0];
#pragma unroll
            for (int j = 1; j < 16; j++) m = fmaxf(m, sv[j]);
            m = fmaxf(m, __shfl_xor_sync(0xffffffffu, m, 1));
            m = fmaxf(m, __shfl_xor_sync(0xffffffffu, m, 2));
            float s = 0.f;
#pragma unroll
            for (int j = 0; j < 16; j++) { sv[j] = __expf(sv[j] - m); s += sv[j]; }
            s += __shfl_xor_sync(0xffffffffu, s, 1);
            s += __shfl_xor_sync(0xffffffffu, s, 2);
            float inv = 1.f / s;
            float* pr = &sm[PS_OFF + hh * 4224 + s_r * 66 + s_c0];
#pragma unroll
            for (int j = 0; j < 8; j++)
                *(ull*)&pr[2 * j] = pk2(sv[2 * j] * inv, sv[2 * j + 1] * inv);
        }
        __syncthreads();

        // ================= AV: o[64][32] -> os_t (aliases qs) =================
        {
            ull av0 = 0ull, av1 = 0ull, av2 = 0ull, av3 = 0ull;
            const float* pr = &sm[PS_OFF + hh * 4224 + s_r * 66];
            const float* vb = &sm[VS_OFF + hh * 2304 + a_d0];
#pragma unroll 8
            for (int j = 0; j < 64; j++) {
                float p = pr[j];
                ull pp = pk2(p, p);
                ulonglong2 v0 = *(const ulonglong2*)(vb + j * 36);
                ulonglong2 v1 = *(const ulonglong2*)(vb + j * 36 + 4);
                ffma2(av0, pp, v0.x); ffma2(av1, pp, v0.y);
                ffma2(av2, pp, v1.x); ffma2(av3, pp, v1.y);
            }
            float* ob = &sm[QS_OFF + hh * 2112];  // os_t[32][66]
            float f0, f1;
            upk2(av0, f0, f1); ob[(a_d0 + 0) * 66 + s_r] = f0; ob[(a_d0 + 1) * 66 + s_r] = f1;
            upk2(av1, f0, f1); ob[(a_d0 + 2) * 66 + s_r] = f0; ob[(a_d0 + 3) * 66 + s_r] = f1;
            upk2(av2, f0, f1); ob[(a_d0 + 4) * 66 + s_r] = f0; ob[(a_d0 + 5) * 66 + s_r] = f1;
            upk2(av3, f0, f1); ob[(a_d0 + 6) * 66 + s_r] = f0; ob[(a_d0 + 7) * 66 + s_r] = f1;
        }
        __syncthreads();

        // ================= incremental out-projection (both heads of pair) ====
        for (int hh2 = 0; hh2 < 2; hh2++) {
            int h = hp * 2 + hh2;
            for (int ck = 0; ck < 2; ck++) {
                // stage wout rows [h*32+ck*16, +16) x 384 (flat, coalesced)
#pragma unroll
                for (int i = 0; i < 12; i++) {
                    int e = i * NT + tid;    // 0..6143
                    sm[WB_OFF + e] = wout[(long)(h * 32 + ck * 16) * 384 + e];
                }
                __syncthreads();
                const float* ob = &sm[QS_OFF + hh2 * 2112];
                const float* wb = &sm[WB_OFF + lane];
#pragma unroll 2
                for (int ddl = 0; ddl < 16; ddl++) {
                    int dd = ck * 16 + ddl;
                    ull a0 = *(const ull*)&ob[dd * 66 + t4];
                    ull a1 = *(const ull*)&ob[dd * 66 + t4 + 2];
#pragma unroll
                    for (int jj = 0; jj < 12; jj++) {
                        float wv = wb[ddl * 384 + 32 * jj];
                        ull ww = pk2(wv, wv);
                        ffma2(oa0[jj], a0, ww);
                        ffma2(oa1[jj], a1, ww);
                    }
                }
                __syncthreads();
            }
        }
    }

    // ================= bias + coalesced store =================
    long ga[4];
#pragma unroll
    for (int i = 0; i < 4; i++) {
        int t = t4 + i;
        ga[i] = gbase + (((t >> 3) * 64) + (t & 7)) * 384;
    }
#pragma unroll
    for (int jj = 0; jj < 12; jj++) {
        int c = lane + 32 * jj;
        float bv = bias[c];
        float v0, v1, v2, v3;
        upk2(oa0[jj], v0, v1);
        upk2(oa1[jj], v2, v3);
        out[ga[0] + c] = v0 + bv;
        out[ga[1] + c] = v1 + bv;
        out[ga[2] + c] = v2 + bv;
        out[ga[3] + c] = v3 + bv;
    }
}

extern "C" void kernel_launch(void* const* d_in, const int* in_sizes, int n_in,
                              void* d_out, int out_size)
{
    const float* x    = (const float*)d_in[0];
    const float* wqkv = (const float*)d_in[1];
    const float* wout = (const float*)d_in[2];
    const float* bout = (const float*)d_in[3];
    float* out = (float*)d_out;

    static bool attr_set = false;
    if (!attr_set) {
        cudaFuncSetAttribute(winattn2,
                             cudaFuncAttributeMaxDynamicSharedMemorySize,
                             SMEM_FLOATS * sizeof(float));
        attr_set = true;
    }
    winattn2<<<2048, NT, SMEM_FLOATS * sizeof(float)>>>(x, wqkv, wout, bout, out);
}

// round 10
// speedup vs baseline: 2.4181x; 2.4181x over previous
#include <cuda_runtime.h>
#include <cuda_bf16.h>
#include <mma.h>
#include <cstdint>

using namespace nvcuda;

#define SCALE 0.17677669529663687f

// ---- scratch (device statics: sanctioned allocation-free workaround) ----
__device__ float g_qkv[150994944];   // [131072][1152] fp32
__device__ float g_ao[50331648];     // [131072][384]  fp32

// ---- gemm smem layout (bytes) ----
#define SA_STR 72                    // bf16 elements per A row
#define SB_STR 136                   // bf16 elements per B row
#define SC_STR 132                   // fp32 elements per C row
#define SA_HI_OFF 0                  // 128*72*2  = 18432
#define SA_LO_OFF 18432
#define SB_HI_OFF 36864              // 64*136*2  = 17408
#define SB_LO_OFF 54272
#define GEMM_SMEM 71680              // >= sC (128*132*4 = 67584)

// ============================================================================
// C[M,Ntot] = A[M,384] * W[384,Ntot] (+bias)
// wmma bf16 hi/lo split, CTA tile 128x128, 8 warps (warp tile 32x64)
// grid = (M/128, Ntot/128), block = 256
// ============================================================================
__global__ void __launch_bounds__(256, 1)
gemm_wmma(const float* __restrict__ A, const float* __restrict__ W,
          const float* __restrict__ bias, float* __restrict__ C, int Ntot)
{
    extern __shared__ char smc[];
    __nv_bfloat16* sAh = (__nv_bfloat16*)(smc + SA_HI_OFF);
    __nv_bfloat16* sAl = (__nv_bfloat16*)(smc + SA_LO_OFF);
    __nv_bfloat16* sBh = (__nv_bfloat16*)(smc + SB_HI_OFF);
    __nv_bfloat16* sBl = (__nv_bfloat16*)(smc + SB_LO_OFF);
    float* sC = (float*)smc;

    const int tid = threadIdx.x, wid = tid >> 5;
    const long m0 = (long)blockIdx.x * 128;
    const int n0 = blockIdx.y * 128;
    const int wm = wid & 3;          // warp row (32 M each)
    const int wn = wid >> 2;         // warp col (64 N each)

    wmma::fragment<wmma::accumulator, 16, 16, 16, float> acc[2][4];
#pragma unroll
    for (int i = 0; i < 2; i++)
#pragma unroll
        for (int j = 0; j < 4; j++) wmma::fill_fragment(acc[i][j], 0.0f);

    for (int kc = 0; kc < 6; kc++) {
        __syncthreads();             // previous iteration's fragment loads done
        // ---- stage A chunk [128][64] as bf16 hi/lo ----
#pragma unroll
        for (int i = 0; i < 8; i++) {
            int e = i * 256 + tid;             // float4 index
            int r = e >> 4, c4 = e & 15;
            float4 v = *(const float4*)&A[(m0 + r) * 384 + kc * 64 + c4 * 4];
            __nv_bfloat162 h01 = __floats2bfloat162_rn(v.x, v.y);
            __nv_bfloat162 h23 = __floats2bfloat162_rn(v.z, v.w);
            __nv_bfloat162 l01 = __floats2bfloat162_rn(v.x - __low2float(h01),
                                                       v.y - __high2float(h01));
            __nv_bfloat162 l23 = __floats2bfloat162_rn(v.z - __low2float(h23),
                                                       v.w - __high2float(h23));
            int o = r * SA_STR + c4 * 4;
            *(uint2*)&sAh[o] = make_uint2(*(uint32_t*)&h01, *(uint32_t*)&h23);
            *(uint2*)&sAl[o] = make_uint2(*(uint32_t*)&l01, *(uint32_t*)&l23);
        }
        // ---- stage B chunk [64][128] as bf16 hi/lo ----
#pragma unroll
        for (int i = 0; i < 8; i++) {
            int e = i * 256 + tid;             // float4 index
            int k = e >> 5, c4 = e & 31;
            float4 v = *(const float4*)&W[(long)(kc * 64 + k) * Ntot + n0 + c4 * 4];
            __nv_bfloat162 h01 = __floats2bfloat162_rn(v.x, v.y);
            __nv_bfloat162 h23 = __floats2bfloat162_rn(v.z, v.w);
            __nv_bfloat162 l01 = __floats2bfloat162_rn(v.x - __low2float(h01),
                                                       v.y - __high2float(h01));
            __nv_bfloat162 l23 = __floats2bfloat162_rn(v.z - __low2float(h23),
                                                       v.w - __high2float(h23));
            int o = k * SB_STR + c4 * 4;
            *(uint2*)&sBh[o] = make_uint2(*(uint32_t*)&h01, *(uint32_t*)&h23);
            *(uint2*)&sBl[o] = make_uint2(*(uint32_t*)&l01, *(uint32_t*)&l23);
        }
        __syncthreads();

        // ---- compute: 4 k16 steps ----
#pragma unroll
        for (int k16 = 0; k16 < 4; k16++) {
            wmma::fragment<wmma::matrix_a, 16, 16, 16, __nv_bfloat16, wmma::row_major> ah[2], al[2];
#pragma unroll
            for (int i = 0; i < 2; i++) {
                const __nv_bfloat16* ap = &sAh[(wm * 32 + i * 16) * SA_STR + k16 * 16];
                wmma::load_matrix_sync(ah[i], ap, SA_STR);
                const __nv_bfloat16* alp = &sAl[(wm * 32 + i * 16) * SA_STR + k16 * 16];
                wmma::load_matrix_sync(al[i], alp, SA_STR);
            }
#pragma unroll
            for (int j = 0; j < 4; j++) {
                wmma::fragment<wmma::matrix_b, 16, 16, 16, __nv_bfloat16, wmma::row_major> bh, bl;
                const __nv_bfloat16* bp = &sBh[(k16 * 16) * SB_STR + wn * 64 + j * 16];
                wmma::load_matrix_sync(bh, bp, SB_STR);
                const __nv_bfloat16* blp = &sBl[(k16 * 16) * SB_STR + wn * 64 + j * 16];
                wmma::load_matrix_sync(bl, blp, SB_STR);
#pragma unroll
                for (int i = 0; i < 2; i++) {
                    wmma::mma_sync(acc[i][j], ah[i], bh, acc[i][j]);
                    wmma::mma_sync(acc[i][j], ah[i], bl, acc[i][j]);
                    wmma::mma_sync(acc[i][j], al[i], bh, acc[i][j]);
                }
            }
        }
    }

    // ---- epilogue: frags -> smem C tile -> bias + coalesced store ----
    __syncthreads();
#pragma unroll
    for (int i = 0; i < 2; i++)
#pragma unroll
        for (int j = 0; j < 4; j++)
            wmma::store_matrix_sync(&sC[(wm * 32 + i * 16) * SC_STR + wn * 64 + j * 16],
                                    acc[i][j], SC_STR, wmma::mem_row_major);
    __syncthreads();
#pragma unroll
    for (int i = 0; i < 16; i++) {
        int e = i * 256 + tid;                 // float4 index
        int r = e >> 5, c4 = e & 31;
        float4 v = *(const float4*)&sC[r * SC_STR + c4 * 4];
        if (bias) {
            float4 bv = *(const float4*)&bias[n0 + c4 * 4];
            v.x += bv.x; v.y += bv.y; v.z += bv.z; v.w += bv.w;
        }
        *(float4*)&C[(m0 + r) * Ntot + n0 + c4 * 4] = v;
    }
}

// ============================================================================
// K2: per-window attention, 12 heads, SIMT (proven structure)
// ============================================================================
__global__ void __launch_bounds__(512, 1)
attn_win()
{
    __shared__ float sq[64 * 33], sk[64 * 33], svv[64 * 36], ps[64 * 68];
    const int tid = threadIdx.x;
    const int n = blockIdx.x;
    const int b = n >> 6, ih = (n >> 3) & 7, iw = n & 7;
    const int tb = (b * 64 + ih * 8) * 64 + iw * 8;
    const int s_r = tid >> 3;
    const int cg8 = tid & 7;
    const int s_c0 = cg8 * 8;
    const int a_d0 = cg8 * 4;
    const long gtr = (long)(tb + (s_r >> 3) * 64 + (s_r & 7));

    for (int h = 0; h < 12; h++) {
        __syncthreads();
#pragma unroll
        for (int i = 0; i < 4; i++) {
            int e = i * 512 + tid;
            int t = e >> 5, c = e & 31;
            long gq = (long)(tb + (t >> 3) * 64 + (t & 7)) * 1152 + h * 32 + c;
            sq[t * 33 + c]  = g_qkv[gq] * SCALE;
            sk[t * 33 + c]  = g_qkv[gq + 384];
            svv[t * 36 + c] = g_qkv[gq + 768];
        }
        __syncthreads();

        float sc[8];
#pragma unroll
        for (int j = 0; j < 8; j++) sc[j] = 0.f;
        const float* qp = &sq[s_r * 33];
        const float* kp = &sk[s_c0 * 33];
#pragma unroll 4
        for (int d = 0; d < 32; d++) {
            float qv = qp[d];
#pragma unroll
            for (int j = 0; j < 8; j++)
                sc[j] = fmaf(qv, kp[j * 33 + d], sc[j]);
        }
        float m = sc[0];
#pragma unroll
        for (int j = 1; j < 8; j++) m = fmaxf(m, sc[j]);
#pragma unroll
        for (int msk = 1; msk < 8; msk <<= 1)
            m = fmaxf(m, __shfl_xor_sync(0xffffffffu, m, msk));
        float ssum = 0.f;
#pragma unroll
        for (int j = 0; j < 8; j++) { sc[j] = __expf(sc[j] - m); ssum += sc[j]; }
#pragma unroll
        for (int msk = 1; msk < 8; msk <<= 1)
            ssum += __shfl_xor_sync(0xffffffffu, ssum, msk);
        float inv = 1.f / ssum;
#pragma unroll
        for (int j = 0; j < 8; j++)
            ps[s_r * 68 + s_c0 + j] = sc[j] * inv;
        __syncthreads();

        float av0 = 0.f, av1 = 0.f, av2 = 0.f, av3 = 0.f;
        const float* pp = &ps[s_r * 68];
#pragma unroll 8
        for (int j = 0; j < 64; j++) {
            float p = pp[j];
            float4 v4 = *(const float4*)&svv[j * 36 + a_d0];
            av0 = fmaf(p, v4.x, av0);
            av1 = fmaf(p, v4.y, av1);
            av2 = fmaf(p, v4.z, av2);
            av3 = fmaf(p, v4.w, av3);
        }
        *(float4*)&g_ao[gtr * 384 + h * 32 + a_d0] = make_float4(av0, av1, av2, av3);
    }
}

// ============================================================================
extern "C" void kernel_launch(void* const* d_in, const int* in_sizes, int n_in,
                              void* d_out, int out_size)
{
    const float* x    = (const float*)d_in[0];
    const float* wqkv = (const float*)d_in[1];
    const float* wout = (const float*)d_in[2];
    const float* bout = (const float*)d_in[3];
    float* out = (float*)d_out;

    static float* p_qkv = nullptr;
    static float* p_ao  = nullptr;
    if (!p_qkv) {
        cudaGetSymbolAddress((void**)&p_qkv, g_qkv);
        cudaGetSymbolAddress((void**)&p_ao,  g_ao);
        cudaFuncSetAttribute(gemm_wmma,
                             cudaFuncAttributeMaxDynamicSharedMemorySize, GEMM_SMEM);
    }

    dim3 g1(1024, 9), g3(1024, 3);
    gemm_wmma<<<g1, 256, GEMM_SMEM>>>(x, wqkv, nullptr, p_qkv, 1152);
    attn_win<<<2048, 512>>>();
    gemm_wmma<<<g3, 256, GEMM_SMEM>>>(p_ao, wout, bout, out, 384);
}

// round 12
// speedup vs baseline: 2.4608x; 1.0177x over previous
#include <cuda_runtime.h>
#include <cuda_bf16.h>
#include <mma.h>
#include <cstdint>

using namespace nvcuda;

#define SCALE 0.17677669529663687f

// ---- persistent scratch (device statics, ~807 MB total = R10 footprint) ----
__device__ float g_qkv[150994944];              // [131072][1152] fp32
__device__ __nv_bfloat16 g_aoh[50331648];       // attn-out hi [131072][384]
__device__ __nv_bfloat16 g_aol[50331648];       // attn-out lo
__device__ __nv_bfloat16 g_wqh[442368];         // w_qkv hi/lo [384][1152]
__device__ __nv_bfloat16 g_wql[442368];
__device__ __nv_bfloat16 g_woh[147456];         // w_out hi/lo [384][384]
__device__ __nv_bfloat16 g_wol[147456];

__device__ __forceinline__ uint32_t s2u(const void* p) {
    uint32_t a;
    asm("{ .reg .u64 t; cvta.to.shared.u64 t, %1; cvt.u32.u64 %0, t; }" : "=r"(a) : "l"(p));
    return a;
}
__device__ __forceinline__ void cpa16(uint32_t dst, const void* src) {
    asm volatile("cp.async.ca.shared.global [%0], [%1], 16;" :: "r"(dst), "l"(src));
}

// ============================================================================
// prep: fp32 -> bf16 hi/lo (vectorized; weights only, tiny)
// ============================================================================
__global__ void conv_hilo(const float* __restrict__ src, __nv_bfloat16* __restrict__ dh,
                          __nv_bfloat16* __restrict__ dl, int n4)
{
    int i = blockIdx.x * blockDim.x + threadIdx.x;
    if (i >= n4) return;
    float4 v = ((const float4*)src)[i];
    __nv_bfloat162 h01 = __floats2bfloat162_rn(v.x, v.y);
    __nv_bfloat162 h23 = __floats2bfloat162_rn(v.z, v.w);
    __nv_bfloat162 l01 = __floats2bfloat162_rn(v.x - __low2float(h01), v.y - __high2float(h01));
    __nv_bfloat162 l23 = __floats2bfloat162_rn(v.z - __low2float(h23), v.w - __high2float(h23));
    ((uint2*)dh)[i] = make_uint2(*(uint32_t*)&h01, *(uint32_t*)&h23);
    ((uint2*)dl)[i] = make_uint2(*(uint32_t*)&l01, *(uint32_t*)&l23);
}

// ---- gemm smem layout (bytes) ----
#define SA_STR 72
#define SB_STR 136
#define SA_H   0                       // 128*72*2 = 18432
#define SA_L   18432
#define SB_BASE 36864                  // 2 buffers x (hi 17408 + lo 17408)
#define SB_SET 34816
#define GEMM_SMEM 106496
#define SC_STR 132                     // fp32 C bounce aliases smem base (67584 B)

// ============================================================================
// C[M,Ntot] = A[M,384] * (Bh+Bl)[384,Ntot] (+bias)
// AFP32: A fp32 converted in-kernel to hi/lo; else A prepped bf16 via cp.async.
// wmma bf16, 3-MMA hi/lo compensation. B double-buffered via cp.async.
// grid=(M/128, Ntot/128), block=256, warp tile 32x64.
// ============================================================================
template <bool AFP32>
__global__ void __launch_bounds__(256, 1)
gemm_bf16(const void* __restrict__ Aarg, const __nv_bfloat16* __restrict__ Alo,
          const __nv_bfloat16* __restrict__ Bh, const __nv_bfloat16* __restrict__ Bl,
          const float* __restrict__ bias, float* __restrict__ C, int Ntot)
{
    extern __shared__ char smc[];
    const int tid = threadIdx.x, wid = tid >> 5;
    const long m0 = (long)blockIdx.x * 128;
    const int n0 = blockIdx.y * 128;
    const int wm = wid & 3, wn = wid >> 2;
    const uint32_t sbase = s2u(smc);

    wmma::fragment<wmma::accumulator, 16, 16, 16, float> acc[2][4];
#pragma unroll
    for (int i = 0; i < 2; i++)
#pragma unroll
        for (int j = 0; j < 4; j++) wmma::fill_fragment(acc[i][j], 0.0f);

    // ---- stage B chunk kc into buffer bi (cp.async, own commit group) ----
    auto stageB = [&](int kc, int bi) {
        uint32_t sbh = sbase + SB_BASE + bi * SB_SET;
        uint32_t sbl = sbh + 17408;
#pragma unroll
        for (int i = 0; i < 4; i++) {
            int e = i * 256 + tid;                 // 0..1023
            int k = e >> 4, c8 = e & 15;
            long go = (long)(kc * 64 + k) * Ntot + n0 + c8 * 8;
            uint32_t so = (uint32_t)(k * SB_STR + c8 * 8) * 2;
            cpa16(sbh + so, Bh + go);
            cpa16(sbl + so, Bl + go);
        }
        asm volatile("cp.async.commit_group;");
    };

    stageB(0, 0);

    for (int kc = 0; kc < 6; kc++) {
        const int bi = kc & 1;
        // ---- stage A chunk kc (single buffer) ----
        if (AFP32) {
            const float* A = (const float*)Aarg;
            __nv_bfloat16* sAh = (__nv_bfloat16*)(smc + SA_H);
            __nv_bfloat16* sAl = (__nv_bfloat16*)(smc + SA_L);
#pragma unroll
            for (int i = 0; i < 8; i++) {
                int e = i * 256 + tid;             // float4 idx
                int r = e >> 4, c4 = e & 15;
                float4 v = *(const float4*)&A[(m0 + r) * 384 + kc * 64 + c4 * 4];
                __nv_bfloat162 h01 = __floats2bfloat162_rn(v.x, v.y);
                __nv_bfloat162 h23 = __floats2bfloat162_rn(v.z, v.w);
                __nv_bfloat162 l01 = __floats2bfloat162_rn(v.x - __low2float(h01),
                                                           v.y - __high2float(h01));
                __nv_bfloat162 l23 = __floats2bfloat162_rn(v.z - __low2float(h23),
                                                           v.w - __high2float(h23));
                int o = r * SA_STR + c4 * 4;
                *(uint2*)&sAh[o] = make_uint2(*(uint32_t*)&h01, *(uint32_t*)&h23);
                *(uint2*)&sAl[o] = make_uint2(*(uint32_t*)&l01, *(uint32_t*)&l23);
            }
        } else {
            const __nv_bfloat16* Ah = (const __nv_bfloat16*)Aarg;
#pragma unroll
            for (int i = 0; i < 4; i++) {
                int e = i * 256 + tid;             // 0..1023
                int r = e >> 3, c8 = e & 7;
                long go = (m0 + r) * 384 + kc * 64 + c8 * 8;
                uint32_t so = (uint32_t)(r * SA_STR + c8 * 8) * 2;
                cpa16(sbase + SA_H + so, Ah + go);
                cpa16(sbase + SA_L + so, Alo + go);
            }
            asm volatile("cp.async.commit_group;");
        }
        // ---- prefetch next B chunk ----
        if (kc < 5) {
            stageB(kc + 1, bi ^ 1);
            asm volatile("cp.async.wait_group 1;");  // B(kc) [+A(kc)] complete
        } else {
            asm volatile("cp.async.wait_group 0;");
        }
        __syncthreads();

        // ---- MMA on chunk kc ----
        const __nv_bfloat16* bAh = (const __nv_bfloat16*)(smc + SA_H);
        const __nv_bfloat16* bAl = (const __nv_bfloat16*)(smc + SA_L);
        const __nv_bfloat16* bBh = (const __nv_bfloat16*)(smc + SB_BASE + bi * SB_SET);
        const __nv_bfloat16* bBl = (const __nv_bfloat16*)(smc + SB_BASE + bi * SB_SET + 17408);
#pragma unroll
        for (int k16 = 0; k16 < 4; k16++) {
            wmma::fragment<wmma::matrix_a, 16, 16, 16, __nv_bfloat16, wmma::row_major> ah[2], al[2];
#pragma unroll
            for (int i = 0; i < 2; i++) {
                wmma::load_matrix_sync(ah[i], &bAh[(wm * 32 + i * 16) * SA_STR + k16 * 16], SA_STR);
                wmma::load_matrix_sync(al[i], &bAl[(wm * 32 + i * 16) * SA_STR + k16 * 16], SA_STR);
            }
#pragma unroll
            for (int j = 0; j < 4; j++) {
                wmma::fragment<wmma::matrix_b, 16, 16, 16, __nv_bfloat16, wmma::row_major> bh, bl;
                wmma::load_matrix_sync(bh, &bBh[(k16 * 16) * SB_STR + wn * 64 + j * 16], SB_STR);
                wmma::load_matrix_sync(bl, &bBl[(k16 * 16) * SB_STR + wn * 64 + j * 16], SB_STR);
#pragma unroll
                for (int i = 0; i < 2; i++) {
                    wmma::mma_sync(acc[i][j], ah[i], bh, acc[i][j]);
                    wmma::mma_sync(acc[i][j], ah[i], bl, acc[i][j]);
                    wmma::mma_sync(acc[i][j], al[i], bh, acc[i][j]);
                }
            }
        }
        __syncthreads();                           // A + B(bi) reusable next iter
    }

    // ---- epilogue: frags -> smem bounce -> bias + coalesced fp32 store ----
    float* sC = (float*)smc;
#pragma unroll
    for (int i = 0; i < 2; i++)
#pragma unroll
        for (int j = 0; j < 4; j++)
            wmma::store_matrix_sync(&sC[(wm * 32 + i * 16) * SC_STR + wn * 64 + j * 16],
                                    acc[i][j], SC_STR, wmma::mem_row_major);
    __syncthreads();
#pragma unroll
    for (int i = 0; i < 16; i++) {
        int e = i * 256 + tid;
        int r = e >> 5, c4 = e & 31;
        float4 v = *(const float4*)&sC[r * SC_STR + c4 * 4];
        if (bias) {
            float4 bv = *(const float4*)&bias[n0 + c4 * 4];
            v.x += bv.x; v.y += bv.y; v.z += bv.z; v.w += bv.w;
        }
        *(float4*)&C[(m0 + r) * Ntot + n0 + c4 * 4] = v;
    }
}

// ============================================================================
// K2: per-window attention; writes bf16 hi/lo (K3's A operand)
// ============================================================================
__global__ void __launch_bounds__(512, 1)
attn_win()
{
    __shared__ float sq[64 * 33], sk[64 * 33], svv[64 * 36], ps[64 * 68];
    const int tid = threadIdx.x;
    const int n = blockIdx.x;
    const int b = n >> 6, ih = (n >> 3) & 7, iw = n & 7;
    const int tb = (b * 64 + ih * 8) * 64 + iw * 8;
    const int s_r = tid >> 3;
    const int cg8 = tid & 7;
    const int s_c0 = cg8 * 8;
    const int a_d0 = cg8 * 4;
    const long gtr = (long)(tb + (s_r >> 3) * 64 + (s_r & 7));

    for (int h = 0; h < 12; h++) {
        __syncthreads();
#pragma unroll
        for (int i = 0; i < 4; i++) {
            int e = i * 512 + tid;
            int t = e >> 5, c = e & 31;
            long gq = (long)(tb + (t >> 3) * 64 + (t & 7)) * 1152 + h * 32 + c;
            sq[t * 33 + c]  = g_qkv[gq] * SCALE;
            sk[t * 33 + c]  = g_qkv[gq + 384];
            svv[t * 36 + c] = g_qkv[gq + 768];
        }
        __syncthreads();

        float sc[8];
#pragma unroll
        for (int j = 0; j < 8; j++) sc[j] = 0.f;
        const float* qp = &sq[s_r * 33];
        const float* kp = &sk[s_c0 * 33];
#pragma unroll 4
        for (int d = 0; d < 32; d++) {
            float qv = qp[d];
#pragma unroll
            for (int j = 0; j < 8; j++)
                sc[j] = fmaf(qv, kp[j * 33 + d], sc[j]);
        }
        float m = sc[0];
#pragma unroll
        for (int j = 1; j < 8; j++) m = fmaxf(m, sc[j]);
#pragma unroll
        for (int msk = 1; msk < 8; msk <<= 1)
            m = fmaxf(m, __shfl_xor_sync(0xffffffffu, m, msk));
        float ssum = 0.f;
#pragma unroll
        for (int j = 0; j < 8; j++) { sc[j] = __expf(sc[j] - m); ssum += sc[j]; }
#pragma unroll
        for (int msk = 1; msk < 8; msk <<= 1)
            ssum += __shfl_xor_sync(0xffffffffu, ssum, msk);
        float inv = 1.f / ssum;
#pragma unroll
        for (int j = 0; j < 8; j++)
            ps[s_r * 68 + s_c0 + j] = sc[j] * inv;
        __syncthreads();

        float av0 = 0.f, av1 = 0.f, av2 = 0.f, av3 = 0.f;
        const float* pp = &ps[s_r * 68];
#pragma unroll 8
        for (int j = 0; j < 64; j++) {
            float p = pp[j];
            float4 v4 = *(const float4*)&svv[j * 36 + a_d0];
            av0 = fmaf(p, v4.x, av0);
            av1 = fmaf(p, v4.y, av1);
            av2 = fmaf(p, v4.z, av2);
            av3 = fmaf(p, v4.w, av3);
        }
        __nv_bfloat162 h01 = __floats2bfloat162_rn(av0, av1);
        __nv_bfloat162 h23 = __floats2bfloat162_rn(av2, av3);
        __nv_bfloat162 l01 = __floats2bfloat162_rn(av0 - __low2float(h01),
                                                   av1 - __high2float(h01));
        __nv_bfloat162 l23 = __floats2bfloat162_rn(av2 - __low2float(h23),
                                                   av3 - __high2float(h23));
        long go = gtr * 384 + h * 32 + a_d0;
        *(uint2*)&g_aoh[go] = make_uint2(*(uint32_t*)&h01, *(uint32_t*)&h23);
        *(uint2*)&g_aol[go] = make_uint2(*(uint32_t*)&l01, *(uint32_t*)&l23);
    }
}

// ============================================================================
extern "C" void kernel_launch(void* const* d_in, const int* in_sizes, int n_in,
                              void* d_out, int out_size)
{
    const float* x    = (const float*)d_in[0];
    const float* wqkv = (const float*)d_in[1];
    const float* wout = (const float*)d_in[2];
    const float* bout = (const float*)d_in[3];
    float* out = (float*)d_out;

    static float* p_qkv = nullptr;
    static __nv_bfloat16 *p_aoh, *p_aol, *p_wqh, *p_wql, *p_woh, *p_wol;
    if (!p_qkv) {
        cudaGetSymbolAddress((void**)&p_qkv, g_qkv);
        cudaGetSymbolAddress((void**)&p_aoh, g_aoh);
        cudaGetSymbolAddress((void**)&p_aol, g_aol);
        cudaGetSymbolAddress((void**)&p_wqh, g_wqh);
        cudaGetSymbolAddress((void**)&p_wql, g_wql);
        cudaGetSymbolAddress((void**)&p_woh, g_woh);
        cudaGetSymbolAddress((void**)&p_wol, g_wol);
        cudaFuncSetAttribute(gemm_bf16<true>,
                             cudaFuncAttributeMaxDynamicSharedMemorySize, GEMM_SMEM);
        cudaFuncSetAttribute(gemm_bf16<false>,
                             cudaFuncAttributeMaxDynamicSharedMemorySize, GEMM_SMEM);
    }

    conv_hilo<<<110592 / 256, 256>>>(wqkv, p_wqh, p_wql, 110592);
    conv_hilo<<<36864 / 256, 256>>>(wout, p_woh, p_wol, 36864);

    dim3 g1(1024, 9), g3(1024, 3);
    gemm_bf16<true><<<g1, 256, GEMM_SMEM>>>(x, nullptr, p_wqh, p_wql, nullptr, p_qkv, 1152);
    attn_win<<<2048, 512>>>();
    gemm_bf16<false><<<g3, 256, GEMM_SMEM>>>(p_aoh, p_aol, p_woh, p_wol, bout, out, 384);
}

// round 13
// speedup vs baseline: 3.3801x; 1.3735x over previous
#include <cuda_runtime.h>
#include <cuda_bf16.h>
#include <mma.h>
#include <cstdint>

using namespace nvcuda;
typedef unsigned long long ull;

#define SCALE 0.17677669529663687f

// ---- persistent scratch (device statics, ~807 MB) ----
__device__ float g_qkv[150994944];              // [131072][1152] fp32
__device__ __nv_bfloat16 g_aoh[50331648];       // attn-out hi [131072][384]
__device__ __nv_bfloat16 g_aol[50331648];       // attn-out lo
__device__ __nv_bfloat16 g_wqh[442368];         // w_qkv hi/lo [384][1152]
__device__ __nv_bfloat16 g_wql[442368];
__device__ __nv_bfloat16 g_woh[147456];         // w_out hi/lo [384][384]
__device__ __nv_bfloat16 g_wol[147456];

__device__ __forceinline__ uint32_t s2u(const void* p) {
    uint32_t a;
    asm("{ .reg .u64 t; cvta.to.shared.u64 t, %1; cvt.u32.u64 %0, t; }" : "=r"(a) : "l"(p));
    return a;
}
__device__ __forceinline__ void cpa16(uint32_t dst, const void* src) {
    asm volatile("cp.async.ca.shared.global [%0], [%1], 16;" :: "r"(dst), "l"(src));
}
__device__ __forceinline__ ull pk2(float lo, float hi) {
    ull r; asm("mov.b64 %0,{%1,%2};" : "=l"(r) : "f"(lo), "f"(hi)); return r;
}
__device__ __forceinline__ void upk2(ull v, float &lo, float &hi) {
    asm("mov.b64 {%0,%1},%2;" : "=f"(lo), "=f"(hi) : "l"(v));
}
__device__ __forceinline__ void ffma2(ull &d, ull a, ull b) {
    asm("fma.rn.f32x2 %0,%1,%2,%0;" : "+l"(d) : "l"(a), "l"(b));
}

// ============================================================================
// prep: fp32 -> bf16 hi/lo (weights only)
// ============================================================================
__global__ void conv_hilo(const float* __restrict__ src, __nv_bfloat16* __restrict__ dh,
                          __nv_bfloat16* __restrict__ dl, int n4)
{
    int i = blockIdx.x * blockDim.x + threadIdx.x;
    if (i >= n4) return;
    float4 v = ((const float4*)src)[i];
    __nv_bfloat162 h01 = __floats2bfloat162_rn(v.x, v.y);
    __nv_bfloat162 h23 = __floats2bfloat162_rn(v.z, v.w);
    __nv_bfloat162 l01 = __floats2bfloat162_rn(v.x - __low2float(h01), v.y - __high2float(h01));
    __nv_bfloat162 l23 = __floats2bfloat162_rn(v.z - __low2float(h23), v.w - __high2float(h23));
    ((uint2*)dh)[i] = make_uint2(*(uint32_t*)&h01, *(uint32_t*)&h23);
    ((uint2*)dl)[i] = make_uint2(*(uint32_t*)&l01, *(uint32_t*)&l23);
}

// ---- gemm smem layout (bytes) ----
#define SA_STR 72
#define SB_STR 136
#define SA_H   0
#define SA_L   18432
#define SB_BASE 36864
#define SB_SET 34816
#define GEMM_SMEM 106496
#define SC_STR 132

// ============================================================================
// GEMM (unchanged from R12): C = A[M,384] * (Bh+Bl)[384,Ntot] (+bias)
// ============================================================================
template <bool AFP32>
__global__ void __launch_bounds__(256, 1)
gemm_bf16(const void* __restrict__ Aarg, const __nv_bfloat16* __restrict__ Alo,
          const __nv_bfloat16* __restrict__ Bh, const __nv_bfloat16* __restrict__ Bl,
          const float* __restrict__ bias, float* __restrict__ C, int Ntot)
{
    extern __shared__ char smc[];
    const int tid = threadIdx.x, wid = tid >> 5;
    const long m0 = (long)blockIdx.x * 128;
    const int n0 = blockIdx.y * 128;
    const int wm = wid & 3, wn = wid >> 2;
    const uint32_t sbase = s2u(smc);

    wmma::fragment<wmma::accumulator, 16, 16, 16, float> acc[2][4];
#pragma unroll
    for (int i = 0; i < 2; i++)
#pragma unroll
        for (int j = 0; j < 4; j++) wmma::fill_fragment(acc[i][j], 0.0f);

    auto stageB = [&](int kc, int bi) {
        uint32_t sbh = sbase + SB_BASE + bi * SB_SET;
        uint32_t sbl = sbh + 17408;
#pragma unroll
        for (int i = 0; i < 4; i++) {
            int e = i * 256 + tid;
            int k = e >> 4, c8 = e & 15;
            long go = (long)(kc * 64 + k) * Ntot + n0 + c8 * 8;
            uint32_t so = (uint32_t)(k * SB_STR + c8 * 8) * 2;
            cpa16(sbh + so, Bh + go);
            cpa16(sbl + so, Bl + go);
        }
        asm volatile("cp.async.commit_group;");
    };

    stageB(0, 0);

    for (int kc = 0; kc < 6; kc++) {
        const int bi = kc & 1;
        if (AFP32) {
            const float* A = (const float*)Aarg;
            __nv_bfloat16* sAh = (__nv_bfloat16*)(smc + SA_H);
            __nv_bfloat16* sAl = (__nv_bfloat16*)(smc + SA_L);
#pragma unroll
            for (int i = 0; i < 8; i++) {
                int e = i * 256 + tid;
                int r = e >> 4, c4 = e & 15;
                float4 v = *(const float4*)&A[(m0 + r) * 384 + kc * 64 + c4 * 4];
                __nv_bfloat162 h01 = __floats2bfloat162_rn(v.x, v.y);
                __nv_bfloat162 h23 = __floats2bfloat162_rn(v.z, v.w);
                __nv_bfloat162 l01 = __floats2bfloat162_rn(v.x - __low2float(h01),
                                                           v.y - __high2float(h01));
                __nv_bfloat162 l23 = __floats2bfloat162_rn(v.z - __low2float(h23),
                                                           v.w - __high2float(h23));
                int o = r * SA_STR + c4 * 4;
                *(uint2*)&sAh[o] = make_uint2(*(uint32_t*)&h01, *(uint32_t*)&h23);
                *(uint2*)&sAl[o] = make_uint2(*(uint32_t*)&l01, *(uint32_t*)&l23);
            }
        } else {
            const __nv_bfloat16* Ah = (const __nv_bfloat16*)Aarg;
#pragma unroll
            for (int i = 0; i < 4; i++) {
                int e = i * 256 + tid;
                int r = e >> 3, c8 = e & 7;
                long go = (m0 + r) * 384 + kc * 64 + c8 * 8;
                uint32_t so = (uint32_t)(r * SA_STR + c8 * 8) * 2;
                cpa16(sbase + SA_H + so, Ah + go);
                cpa16(sbase + SA_L + so, Alo + go);
            }
            asm volatile("cp.async.commit_group;");
        }
        if (kc < 5) {
            stageB(kc + 1, bi ^ 1);
            asm volatile("cp.async.wait_group 1;");
        } else {
            asm volatile("cp.async.wait_group 0;");
        }
        __syncthreads();

        const __nv_bfloat16* bAh = (const __nv_bfloat16*)(smc + SA_H);
        const __nv_bfloat16* bAl = (const __nv_bfloat16*)(smc + SA_L);
        const __nv_bfloat16* bBh = (const __nv_bfloat16*)(smc + SB_BASE + bi * SB_SET);
        const __nv_bfloat16* bBl = (const __nv_bfloat16*)(smc + SB_BASE + bi * SB_SET + 17408);
#pragma unroll
        for (int k16 = 0; k16 < 4; k16++) {
            wmma::fragment<wmma::matrix_a, 16, 16, 16, __nv_bfloat16, wmma::row_major> ah[2], al[2];
#pragma unroll
            for (int i = 0; i < 2; i++) {
                wmma::load_matrix_sync(ah[i], &bAh[(wm * 32 + i * 16) * SA_STR + k16 * 16], SA_STR);
                wmma::load_matrix_sync(al[i], &bAl[(wm * 32 + i * 16) * SA_STR + k16 * 16], SA_STR);
            }
#pragma unroll
            for (int j = 0; j < 4; j++) {
                wmma::fragment<wmma::matrix_b, 16, 16, 16, __nv_bfloat16, wmma::row_major> bh, bl;
                wmma::load_matrix_sync(bh, &bBh[(k16 * 16) * SB_STR + wn * 64 + j * 16], SB_STR);
                wmma::load_matrix_sync(bl, &bBl[(k16 * 16) * SB_STR + wn * 64 + j * 16], SB_STR);
#pragma unroll
                for (int i = 0; i < 2; i++) {
                    wmma::mma_sync(acc[i][j], ah[i], bh, acc[i][j]);
                    wmma::mma_sync(acc[i][j], ah[i], bl, acc[i][j]);
                    wmma::mma_sync(acc[i][j], al[i], bh, acc[i][j]);
                }
            }
        }
        __syncthreads();
    }

    float* sC = (float*)smc;
#pragma unroll
    for (int i = 0; i < 2; i++)
#pragma unroll
        for (int j = 0; j < 4; j++)
            wmma::store_matrix_sync(&sC[(wm * 32 + i * 16) * SC_STR + wn * 64 + j * 16],
                                    acc[i][j], SC_STR, wmma::mem_row_major);
    __syncthreads();
#pragma unroll
    for (int i = 0; i < 16; i++) {
        int e = i * 256 + tid;
        int r = e >> 5, c4 = e & 31;
        float4 v = *(const float4*)&sC[r * SC_STR + c4 * 4];
        if (bias) {
            float4 bv = *(const float4*)&bias[n0 + c4 * 4];
            v.x += bv.x; v.y += bv.y; v.z += bv.z; v.w += bv.w;
        }
        *(float4*)&C[(m0 + r) * Ntot + n0 + c4 * 4] = v;
    }
}

// ============================================================================
// K2: register-tiled windowed attention, 4 heads in flight.
// thread: scores 4 rows x 8 cols (cols 8j+cg8), AV 2 rows x 8 dims (ffma2).
// ============================================================================
#define HS 2308                        // per-head slab stride (floats), 2308%32=4
#define SQ_OFF 0                       // 4*2308
#define SK_OFF 9232
#define SV_OFF 18464
#define PS_OFF 27696                   // ps[4][64][68]
#define ATTN_SMEM_FLOATS 45104         // 180,416 bytes

__global__ void __launch_bounds__(512, 1)
attn_win()
{
    extern __shared__ float sm[];
    const int tid = threadIdx.x;
    const int n = blockIdx.x;
    const int b = n >> 6, ih = (n >> 3) & 7, iw = n & 7;
    const int tb = (b * 64 + ih * 8) * 64 + iw * 8;

    const int hq = tid >> 7;           // head within quad
    const int st = tid & 127;
    const int rg = st >> 3;            // score row group (4 rows)
    const int cg8 = st & 7;            // score col lane
    const int r0 = rg * 4;
    const int rql = st >> 2;           // AV row pair base /2
    const int dq = st & 3;             // AV dim group (8 dims)

    for (int hp = 0; hp < 3; hp++) {
        const int h0 = hp * 4;
        __syncthreads();               // prior quad's sv/ps readers done
        // ---- stage q,k,v for 4 heads (float4, coalesced 128B segments) ----
#pragma unroll
        for (int i = 0; i < 12; i++) {
            int e = i * 512 + tid;     // 0..6143 float4 units
            int c8 = e & 7;
            int r = e >> 3;
            int hh4 = r & 3; r >>= 2;
            int p = r % 3;
            int t = r / 3;
            long gf4 = (long)(tb + (t >> 3) * 64 + (t & 7)) * 288 + p * 96 + (h0 + hh4) * 8 + c8;
            float4 v = ((const float4*)g_qkv)[gf4];
            int base = (p == 0) ? SQ_OFF : (p == 1 ? SK_OFF : SV_OFF);
            if (p == 0) { v.x *= SCALE; v.y *= SCALE; v.z *= SCALE; v.w *= SCALE; }
            *(float4*)&sm[base + hh4 * HS + t * 36 + c8 * 4] = v;
        }
        __syncthreads();

        // ---- scores: 4 rows x 8 cols, d-vectorized float4 ----
        float acc[4][8];
#pragma unroll
        for (int i = 0; i < 4; i++)
#pragma unroll
            for (int j = 0; j < 8; j++) acc[i][j] = 0.f;

        const float* qb = &sm[SQ_OFF + hq * HS];
        const float* kb = &sm[SK_OFF + hq * HS];
#pragma unroll
        for (int dblk = 0; dblk < 8; dblk++) {
            float4 qv[4];
#pragma unroll
            for (int i = 0; i < 4; i++)
                qv[i] = *(const float4*)&qb[(r0 + i) * 36 + dblk * 4];
#pragma unroll
            for (int j = 0; j < 8; j++) {
                float4 kv = *(const float4*)&kb[(j * 8 + cg8) * 36 + dblk * 4];
#pragma unroll
                for (int i = 0; i < 4; i++) {
                    acc[i][j] = fmaf(qv[i].x, kv.x, acc[i][j]);
                    acc[i][j] = fmaf(qv[i].y, kv.y, acc[i][j]);
                    acc[i][j] = fmaf(qv[i].z, kv.z, acc[i][j]);
                    acc[i][j] = fmaf(qv[i].w, kv.w, acc[i][j]);
                }
            }
        }

        // ---- softmax per row (8-lane shfl groups over cg8) ----
        float* psb = &sm[PS_OFF + hq * 4352];
#pragma unroll
        for (int i = 0; i < 4; i++) {
            float m = acc[i][0];
#pragma unroll
            for (int j = 1; j < 8; j++) m = fmaxf(m, acc[i][j]);
            m = fmaxf(m, __shfl_xor_sync(0xffffffffu, m, 1));
            m = fmaxf(m, __shfl_xor_sync(0xffffffffu, m, 2));
            m = fmaxf(m, __shfl_xor_sync(0xffffffffu, m, 4));
            float s = 0.f;
#pragma unroll
            for (int j = 0; j < 8; j++) { acc[i][j] = __expf(acc[i][j] - m); s += acc[i][j]; }
            s += __shfl_xor_sync(0xffffffffu, s, 1);
            s += __shfl_xor_sync(0xffffffffu, s, 2);
            s += __shfl_xor_sync(0xffffffffu, s, 4);
            float inv = 1.f / s;
#pragma unroll
            for (int j = 0; j < 8; j++)
                psb[(r0 + i) * 68 + j * 8 + cg8] = acc[i][j] * inv;
        }
        __syncthreads();

        // ---- AV: 2 rows x 8 dims, f32x2 ----
        ull oa[2][4];
#pragma unroll
        for (int i = 0; i < 2; i++)
#pragma unroll
            for (int j = 0; j < 4; j++) oa[i][j] = 0ull;

        const float* vb = &sm[SV_OFF + hq * HS + dq * 8];
        const float* p0 = &sm[PS_OFF + hq * 4352 + (rql * 2) * 68];
        const float* p1 = p0 + 68;
#pragma unroll 8
        for (int j = 0; j < 64; j++) {
            ulonglong2 va = *(const ulonglong2*)(vb + j * 36);
            ulonglong2 vc = *(const ulonglong2*)(vb + j * 36 + 4);
            ull P0 = pk2(p0[j], p0[j]);
            ull P1 = pk2(p1[j], p1[j]);
            ffma2(oa[0][0], P0, va.x); ffma2(oa[0][1], P0, va.y);
            ffma2(oa[0][2], P0, vc.x); ffma2(oa[0][3], P0, vc.y);
            ffma2(oa[1][0], P1, va.x); ffma2(oa[1][1], P1, va.y);
            ffma2(oa[1][2], P1, vc.x); ffma2(oa[1][3], P1, vc.y);
        }
        // ---- bf16 hi/lo output ----
#pragma unroll
        for (int i = 0; i < 2; i++) {
            int row = rql * 2 + i;
            long gtok = tb + (row >> 3) * 64 + (row & 7);
            long go = gtok * 384 + (h0 + hq) * 32 + dq * 8;
            float o[8];
            upk2(oa[i][0], o[0], o[1]); upk2(oa[i][1], o[2], o[3]);
            upk2(oa[i][2], o[4], o[5]); upk2(oa[i][3], o[6], o[7]);
            uint32_t hw[4], lw[4];
#pragma unroll
            for (int q2 = 0; q2 < 4; q2++) {
                __nv_bfloat162 h2 = __floats2bfloat162_rn(o[2 * q2], o[2 * q2 + 1]);
                __nv_bfloat162 l2 = __floats2bfloat162_rn(o[2 * q2] - __low2float(h2),
                                                          o[2 * q2 + 1] - __high2float(h2));
                hw[q2] = *(uint32_t*)&h2;
                lw[q2] = *(uint32_t*)&l2;
            }
            *(uint4*)&g_aoh[go] = make_uint4(hw[0], hw[1], hw[2], hw[3]);
            *(uint4*)&g_aol[go] = make_uint4(lw[0], lw[1], lw[2], lw[3]);
        }
    }
}

// ============================================================================
extern "C" void kernel_launch(void* const* d_in, const int* in_sizes, int n_in,
                              void* d_out, int out_size)
{
    const float* x    = (const float*)d_in[0];
    const float* wqkv = (const float*)d_in[1];
    const float* wout = (const float*)d_in[2];
    const float* bout = (const float*)d_in[3];
    float* out = (float*)d_out;

    static float* p_qkv = nullptr;
    static __nv_bfloat16 *p_aoh, *p_aol, *p_wqh, *p_wql, *p_woh, *p_wol;
    if (!p_qkv) {
        cudaGetSymbolAddress((void**)&p_qkv, g_qkv);
        cudaGetSymbolAddress((void**)&p_aoh, g_aoh);
        cudaGetSymbolAddress((void**)&p_aol, g_aol);
        cudaGetSymbolAddress((void**)&p_wqh, g_wqh);
        cudaGetSymbolAddress((void**)&p_wql, g_wql);
        cudaGetSymbolAddress((void**)&p_woh, g_woh);
        cudaGetSymbolAddress((void**)&p_wol, g_wol);
        cudaFuncSetAttribute(gemm_bf16<true>,
                             cudaFuncAttributeMaxDynamicSharedMemorySize, GEMM_SMEM);
        cudaFuncSetAttribute(gemm_bf16<false>,
                             cudaFuncAttributeMaxDynamicSharedMemorySize, GEMM_SMEM);
        cudaFuncSetAttribute(attn_win,
                             cudaFuncAttributeMaxDynamicSharedMemorySize,
                             ATTN_SMEM_FLOATS * sizeof(float));
    }

    conv_hilo<<<110592 / 256, 256>>>(wqkv, p_wqh, p_wql, 110592);
    conv_hilo<<<36864 / 256, 256>>>(wout, p_woh, p_wol, 36864);

    dim3 g1(1024, 9), g3(1024, 3);
    gemm_bf16<true><<<g1, 256, GEMM_SMEM>>>(x, nullptr, p_wqh, p_wql, nullptr, p_qkv, 1152);
    attn_win<<<2048, 512, ATTN_SMEM_FLOATS * sizeof(float)>>>();
    gemm_bf16<false><<<g3, 256, GEMM_SMEM>>>(p_aoh, p_aol, p_woh, p_wol, bout, out, 384);
}

// round 14
// speedup vs baseline: 3.5530x; 1.0512x over previous
#include <cuda_runtime.h>
#include <cuda_bf16.h>
#include <mma.h>
#include <cstdint>

using namespace nvcuda;
typedef unsigned long long ull;

#define SCALE 0.17677669529663687f

// ---- persistent scratch (device statics, ~807 MB — same as R12/R13) ----
__device__ float g_qkv[150994944];              // [131072][1152] fp32
__device__ __nv_bfloat16 g_aoh[50331648];       // x-hi (K1 input) then attn-out hi
__device__ __nv_bfloat16 g_aol[50331648];       // x-lo (K1 input) then attn-out lo
__device__ __nv_bfloat16 g_wqh[442368];         // w_qkv hi/lo [384][1152]
__device__ __nv_bfloat16 g_wql[442368];
__device__ __nv_bfloat16 g_woh[147456];         // w_out hi/lo [384][384]
__device__ __nv_bfloat16 g_wol[147456];

__device__ __forceinline__ uint32_t s2u(const void* p) {
    uint32_t a;
    asm("{ .reg .u64 t; cvta.to.shared.u64 t, %1; cvt.u32.u64 %0, t; }" : "=r"(a) : "l"(p));
    return a;
}
__device__ __forceinline__ void cpa16(uint32_t dst, const void* src) {
    asm volatile("cp.async.ca.shared.global [%0], [%1], 16;" :: "r"(dst), "l"(src));
}
__device__ __forceinline__ ull pk2(float lo, float hi) {
    ull r; asm("mov.b64 %0,{%1,%2};" : "=l"(r) : "f"(lo), "f"(hi)); return r;
}
__device__ __forceinline__ void upk2(ull v, float &lo, float &hi) {
    asm("mov.b64 {%0,%1},%2;" : "=f"(lo), "=f"(hi) : "l"(v));
}
__device__ __forceinline__ void ffma2(ull &d, ull a, ull b) {
    asm("fma.rn.f32x2 %0,%1,%2,%0;" : "+l"(d) : "l"(a), "l"(b));
}

// ============================================================================
// prep: fp32 -> bf16 hi/lo
// ============================================================================
__global__ void conv_hilo(const float* __restrict__ src, __nv_bfloat16* __restrict__ dh,
                          __nv_bfloat16* __restrict__ dl, int n4)
{
    int i = blockIdx.x * blockDim.x + threadIdx.x;
    if (i >= n4) return;
    float4 v = ((const float4*)src)[i];
    __nv_bfloat162 h01 = __floats2bfloat162_rn(v.x, v.y);
    __nv_bfloat162 h23 = __floats2bfloat162_rn(v.z, v.w);
    __nv_bfloat162 l01 = __floats2bfloat162_rn(v.x - __low2float(h01), v.y - __high2float(h01));
    __nv_bfloat162 l23 = __floats2bfloat162_rn(v.z - __low2float(h23), v.w - __high2float(h23));
    ((uint2*)dh)[i] = make_uint2(*(uint32_t*)&h01, *(uint32_t*)&h23);
    ((uint2*)dl)[i] = make_uint2(*(uint32_t*)&l01, *(uint32_t*)&l23);
}

// ---- gemm smem layout (bytes) ----
#define SA_STR 72
#define SB_STR 136
#define SA_H   0
#define SA_L   18432
#define SB_BASE 36864
#define SB_SET 34816
#define GEMM_SMEM 106496
#define SC_STR 132

// ============================================================================
// C[M,Ntot] = (Ah+Al)[M,384] * (Bh+Bl)[384,Ntot] (+bias)
// Pure cp.async staging (A single-buffered, B double-buffered), 3-MMA hi/lo.
// grid=(M/128, Ntot/128), block=256, 2 CTAs/SM target, warp tile 32x64.
// ============================================================================
__global__ void __launch_bounds__(256, 2)
gemm_bf16(const __nv_bfloat16* __restrict__ Ah, const __nv_bfloat16* __restrict__ Al,
          const __nv_bfloat16* __restrict__ Bh, const __nv_bfloat16* __restrict__ Bl,
          const float* __restrict__ bias, float* __restrict__ C, int Ntot)
{
    extern __shared__ char smc[];
    const int tid = threadIdx.x, wid = tid >> 5;
    const long m0 = (long)blockIdx.x * 128;
    const int n0 = blockIdx.y * 128;
    const int wm = wid & 3, wn = wid >> 2;
    const uint32_t sbase = s2u(smc);

    wmma::fragment<wmma::accumulator, 16, 16, 16, float> acc[2][4];
#pragma unroll
    for (int i = 0; i < 2; i++)
#pragma unroll
        for (int j = 0; j < 4; j++) wmma::fill_fragment(acc[i][j], 0.0f);

    auto stageB = [&](int kc, int bi) {
        uint32_t sbh = sbase + SB_BASE + bi * SB_SET;
        uint32_t sbl = sbh + 17408;
#pragma unroll
        for (int i = 0; i < 4; i++) {
            int e = i * 256 + tid;
            int k = e >> 4, c8 = e & 15;
            long go = (long)(kc * 64 + k) * Ntot + n0 + c8 * 8;
            uint32_t so = (uint32_t)(k * SB_STR + c8 * 8) * 2;
            cpa16(sbh + so, Bh + go);
            cpa16(sbl + so, Bl + go);
        }
        asm volatile("cp.async.commit_group;");
    };

    stageB(0, 0);

    for (int kc = 0; kc < 6; kc++) {
        const int bi = kc & 1;
        // ---- stage A chunk kc (single buffer, cp.async) ----
#pragma unroll
        for (int i = 0; i < 4; i++) {
            int e = i * 256 + tid;
            int r = e >> 3, c8 = e & 7;
            long go = (m0 + r) * 384 + kc * 64 + c8 * 8;
            uint32_t so = (uint32_t)(r * SA_STR + c8 * 8) * 2;
            cpa16(sbase + SA_H + so, Ah + go);
            cpa16(sbase + SA_L + so, Al + go);
        }
        asm volatile("cp.async.commit_group;");
        // ---- prefetch next B chunk, then wait for A(kc)+B(kc) ----
        if (kc < 5) {
            stageB(kc + 1, bi ^ 1);
            asm volatile("cp.async.wait_group 1;");
        } else {
            asm volatile("cp.async.wait_group 0;");
        }
        __syncthreads();

        // ---- MMA on chunk kc ----
        const __nv_bfloat16* bAh = (const __nv_bfloat16*)(smc + SA_H);
        const __nv_bfloat16* bAl = (const __nv_bfloat16*)(smc + SA_L);
        const __nv_bfloat16* bBh = (const __nv_bfloat16*)(smc + SB_BASE + bi * SB_SET);
        const __nv_bfloat16* bBl = (const __nv_bfloat16*)(smc + SB_BASE + bi * SB_SET + 17408);
#pragma unroll
        for (int k16 = 0; k16 < 4; k16++) {
            wmma::fragment<wmma::matrix_a, 16, 16, 16, __nv_bfloat16, wmma::row_major> ah[2], al[2];
#pragma unroll
            for (int i = 0; i < 2; i++) {
                wmma::load_matrix_sync(ah[i], &bAh[(wm * 32 + i * 16) * SA_STR + k16 * 16], SA_STR);
                wmma::load_matrix_sync(al[i], &bAl[(wm * 32 + i * 16) * SA_STR + k16 * 16], SA_STR);
            }
#pragma unroll
            for (int j = 0; j < 4; j++) {
                wmma::fragment<wmma::matrix_b, 16, 16, 16, __nv_bfloat16, wmma::row_major> bh, bl;
                wmma::load_matrix_sync(bh, &bBh[(k16 * 16) * SB_STR + wn * 64 + j * 16], SB_STR);
                wmma::load_matrix_sync(bl, &bBl[(k16 * 16) * SB_STR + wn * 64 + j * 16], SB_STR);
#pragma unroll
                for (int i = 0; i < 2; i++) {
                    wmma::mma_sync(acc[i][j], ah[i], bh, acc[i][j]);
                    wmma::mma_sync(acc[i][j], ah[i], bl, acc[i][j]);
                    wmma::mma_sync(acc[i][j], al[i], bh, acc[i][j]);
                }
            }
        }
        __syncthreads();   // A + B(bi) reusable next iteration
    }

    // ---- epilogue: frags -> smem bounce -> bias + coalesced fp32 store ----
    float* sC = (float*)smc;
#pragma unroll
    for (int i = 0; i < 2; i++)
#pragma unroll
        for (int j = 0; j < 4; j++)
            wmma::store_matrix_sync(&sC[(wm * 32 + i * 16) * SC_STR + wn * 64 + j * 16],
                                    acc[i][j], SC_STR, wmma::mem_row_major);
    __syncthreads();
#pragma unroll
    for (int i = 0; i < 16; i++) {
        int e = i * 256 + tid;
        int r = e >> 5, c4 = e & 31;
        float4 v = *(const float4*)&sC[r * SC_STR + c4 * 4];
        if (bias) {
            float4 bv = *(const float4*)&bias[n0 + c4 * 4];
            v.x += bv.x; v.y += bv.y; v.z += bv.z; v.w += bv.w;
        }
        *(float4*)&C[(m0 + r) * Ntot + n0 + c4 * 4] = v;
    }
}

// ============================================================================
// K2: register-tiled windowed attention, 4 heads in flight (unchanged R13)
// ============================================================================
#define HS 2308
#define SQ_OFF 0
#define SK_OFF 9232
#define SV_OFF 18464
#define PS_OFF 27696
#define ATTN_SMEM_FLOATS 45104

__global__ void __launch_bounds__(512, 1)
attn_win()
{
    extern __shared__ float sm[];
    const int tid = threadIdx.x;
    const int n = blockIdx.x;
    const int b = n >> 6, ih = (n >> 3) & 7, iw = n & 7;
    const int tb = (b * 64 + ih * 8) * 64 + iw * 8;

    const int hq = tid >> 7;
    const int st = tid & 127;
    const int rg = st >> 3;
    const int cg8 = st & 7;
    const int r0 = rg * 4;
    const int rql = st >> 2;
    const int dq = st & 3;

    for (int hp = 0; hp < 3; hp++) {
        const int h0 = hp * 4;
        __syncthreads();
#pragma unroll
        for (int i = 0; i < 12; i++) {
            int e = i * 512 + tid;
            int c8 = e & 7;
            int r = e >> 3;
            int hh4 = r & 3; r >>= 2;
            int p = r % 3;
            int t = r / 3;
            long gf4 = (long)(tb + (t >> 3) * 64 + (t & 7)) * 288 + p * 96 + (h0 + hh4) * 8 + c8;
            float4 v = ((const float4*)g_qkv)[gf4];
            int base = (p == 0) ? SQ_OFF : (p == 1 ? SK_OFF : SV_OFF);
            if (p == 0) { v.x *= SCALE; v.y *= SCALE; v.z *= SCALE; v.w *= SCALE; }
            *(float4*)&sm[base + hh4 * HS + t * 36 + c8 * 4] = v;
        }
        __syncthreads();

        float acc[4][8];
#pragma unroll
        for (int i = 0; i < 4; i++)
#pragma unroll
            for (int j = 0; j < 8; j++) acc[i][j] = 0.f;

        const float* qb = &sm[SQ_OFF + hq * HS];
        const float* kb = &sm[SK_OFF + hq * HS];
#pragma unroll
        for (int dblk = 0; dblk < 8; dblk++) {
            float4 qv[4];
#pragma unroll
            for (int i = 0; i < 4; i++)
                qv[i] = *(const float4*)&qb[(r0 + i) * 36 + dblk * 4];
#pragma unroll
            for (int j = 0; j < 8; j++) {
                float4 kv = *(const float4*)&kb[(j * 8 + cg8) * 36 + dblk * 4];
#pragma unroll
                for (int i = 0; i < 4; i++) {
                    acc[i][j] = fmaf(qv[i].x, kv.x, acc[i][j]);
                    acc[i][j] = fmaf(qv[i].y, kv.y, acc[i][j]);
                    acc[i][j] = fmaf(qv[i].z, kv.z, acc[i][j]);
                    acc[i][j] = fmaf(qv[i].w, kv.w, acc[i][j]);
                }
            }
        }

        float* psb = &sm[PS_OFF + hq * 4352];
#pragma unroll
        for (int i = 0; i < 4; i++) {
            float m = acc[i][0];
#pragma unroll
            for (int j = 1; j < 8; j++) m = fmaxf(m, acc[i][j]);
            m = fmaxf(m, __shfl_xor_sync(0xffffffffu, m, 1));
            m = fmaxf(m, __shfl_xor_sync(0xffffffffu, m, 2));
            m = fmaxf(m, __shfl_xor_sync(0xffffffffu, m, 4));
            float s = 0.f;
#pragma unroll
            for (int j = 0; j < 8; j++) { acc[i][j] = __expf(acc[i][j] - m); s += acc[i][j]; }
            s += __shfl_xor_sync(0xffffffffu, s, 1);
            s += __shfl_xor_sync(0xffffffffu, s, 2);
            s += __shfl_xor_sync(0xffffffffu, s, 4);
            float inv = 1.f / s;
#pragma unroll
            for (int j = 0; j < 8; j++)
                psb[(r0 + i) * 68 + j * 8 + cg8] = acc[i][j] * inv;
        }
        __syncthreads();

        ull oa[2][4];
#pragma unroll
        for (int i = 0; i < 2; i++)
#pragma unroll
            for (int j = 0; j < 4; j++) oa[i][j] = 0ull;

        const float* vb = &sm[SV_OFF + hq * HS + dq * 8];
        const float* p0 = &sm[PS_OFF + hq * 4352 + (rql * 2) * 68];
        const float* p1 = p0 + 68;
#pragma unroll 8
        for (int j = 0; j < 64; j++) {
            ulonglong2 va = *(const ulonglong2*)(vb + j * 36);
            ulonglong2 vc = *(const ulonglong2*)(vb + j * 36 + 4);
            ull P0 = pk2(p0[j], p0[j]);
            ull P1 = pk2(p1[j], p1[j]);
            ffma2(oa[0][0], P0, va.x); ffma2(oa[0][1], P0, va.y);
            ffma2(oa[0][2], P0, vc.x); ffma2(oa[0][3], P0, vc.y);
            ffma2(oa[1][0], P1, va.x); ffma2(oa[1][1], P1, va.y);
            ffma2(oa[1][2], P1, vc.x); ffma2(oa[1][3], P1, vc.y);
        }
#pragma unroll
        for (int i = 0; i < 2; i++) {
            int row = rql * 2 + i;
            long gtok = tb + (row >> 3) * 64 + (row & 7);
            long go = gtok * 384 + (h0 + hq) * 32 + dq * 8;
            float o[8];
            upk2(oa[i][0], o[0], o[1]); upk2(oa[i][1], o[2], o[3]);
            upk2(oa[i][2], o[4], o[5]); upk2(oa[i][3], o[6], o[7]);
            uint32_t hw[4], lw[4];
#pragma unroll
            for (int q2 = 0; q2 < 4; q2++) {
                __nv_bfloat162 h2 = __floats2bfloat162_rn(o[2 * q2], o[2 * q2 + 1]);
                __nv_bfloat162 l2 = __floats2bfloat162_rn(o[2 * q2] - __low2float(h2),
                                                          o[2 * q2 + 1] - __high2float(h2));
                hw[q2] = *(uint32_t*)&h2;
                lw[q2] = *(uint32_t*)&l2;
            }
            *(uint4*)&g_aoh[go] = make_uint4(hw[0], hw[1], hw[2], hw[3]);
            *(uint4*)&g_aol[go] = make_uint4(lw[0], lw[1], lw[2], lw[3]);
        }
    }
}

// ============================================================================
extern "C" void kernel_launch(void* const* d_in, const int* in_sizes, int n_in,
                              void* d_out, int out_size)
{
    const float* x    = (const float*)d_in[0];
    const float* wqkv = (const float*)d_in[1];
    const float* wout = (const float*)d_in[2];
    const float* bout = (const float*)d_in[3];
    float* out = (float*)d_out;

    static float* p_qkv = nullptr;
    static __nv_bfloat16 *p_aoh, *p_aol, *p_wqh, *p_wql, *p_woh, *p_wol;
    if (!p_qkv) {
        cudaGetSymbolAddress((void**)&p_qkv, g_qkv);
        cudaGetSymbolAddress((void**)&p_aoh, g_aoh);
        cudaGetSymbolAddress((void**)&p_aol, g_aol);
        cudaGetSymbolAddress((void**)&p_wqh, g_wqh);
        cudaGetSymbolAddress((void**)&p_wql, g_wql);
        cudaGetSymbolAddress((void**)&p_woh, g_woh);
        cudaGetSymbolAddress((void**)&p_wol, g_wol);
        cudaFuncSetAttribute(gemm_bf16,
                             cudaFuncAttributeMaxDynamicSharedMemorySize, GEMM_SMEM);
        cudaFuncSetAttribute(attn_win,
                             cudaFuncAttributeMaxDynamicSharedMemorySize,
                             ATTN_SMEM_FLOATS * sizeof(float));
    }

    // x -> bf16 hi/lo staged in g_aoh/g_aol (dead until attn_win rewrites them)
    conv_hilo<<<12582912 / 256, 256>>>(x, p_aoh, p_aol, 12582912);
    conv_hilo<<<110592 / 256, 256>>>(wqkv, p_wqh, p_wql, 110592);
    conv_hilo<<<36864 / 256, 256>>>(wout, p_woh, p_wol, 36864);

    dim3 g1(1024, 9), g3(1024, 3);
    gemm_bf16<<<g1, 256, GEMM_SMEM>>>(p_aoh, p_aol, p_wqh, p_wql, nullptr, p_qkv, 1152);
    attn_win<<<2048, 512, ATTN_SMEM_FLOATS * sizeof(float)>>>();
    gemm_bf16<<<g3, 256, GEMM_SMEM>>>(p_aoh, p_aol, p_woh, p_wol, bout, out, 384);
}

// round 15
// speedup vs baseline: 3.8765x; 1.0911x over previous
#include <cuda_runtime.h>
#include <cuda_bf16.h>
#include <mma.h>
#include <cstdint>

using namespace nvcuda;
typedef unsigned long long ull;

#define SCALE 0.17677669529663687f

// ---- persistent scratch (device statics, ~807 MB) ----
__device__ float g_qkv[150994944];              // [131072][1152] fp32
__device__ __nv_bfloat16 g_aoh[50331648];       // x-hi (K1 input) then attn-out hi
__device__ __nv_bfloat16 g_aol[50331648];       // x-lo (K1 input) then attn-out lo
__device__ __nv_bfloat16 g_wqh[442368];         // w_qkv hi/lo [384][1152]
__device__ __nv_bfloat16 g_wql[442368];
__device__ __nv_bfloat16 g_woh[147456];         // w_out hi/lo [384][384]
__device__ __nv_bfloat16 g_wol[147456];

__device__ __forceinline__ uint32_t s2u(const void* p) {
    uint32_t a;
    asm("{ .reg .u64 t; cvta.to.shared.u64 t, %1; cvt.u32.u64 %0, t; }" : "=r"(a) : "l"(p));
    return a;
}
__device__ __forceinline__ void cpa16(uint32_t dst, const void* src) {
    asm volatile("cp.async.ca.shared.global [%0], [%1], 16;" :: "r"(dst), "l"(src));
}
__device__ __forceinline__ ull pk2(float lo, float hi) {
    ull r; asm("mov.b64 %0,{%1,%2};" : "=l"(r) : "f"(lo), "f"(hi)); return r;
}
__device__ __forceinline__ void upk2(ull v, float &lo, float &hi) {
    asm("mov.b64 {%0,%1},%2;" : "=f"(lo), "=f"(hi) : "l"(v));
}
__device__ __forceinline__ void ffma2(ull &d, ull a, ull b) {
    asm("fma.rn.f32x2 %0,%1,%2,%0;" : "+l"(d) : "l"(a), "l"(b));
}

// ============================================================================
// prep: fp32 -> bf16 hi/lo
// ============================================================================
__global__ void conv_hilo(const float* __restrict__ src, __nv_bfloat16* __restrict__ dh,
                          __nv_bfloat16* __restrict__ dl, int n4)
{
    int i = blockIdx.x * blockDim.x + threadIdx.x;
    if (i >= n4) return;
    float4 v = ((const float4*)src)[i];
    __nv_bfloat162 h01 = __floats2bfloat162_rn(v.x, v.y);
    __nv_bfloat162 h23 = __floats2bfloat162_rn(v.z, v.w);
    __nv_bfloat162 l01 = __floats2bfloat162_rn(v.x - __low2float(h01), v.y - __high2float(h01));
    __nv_bfloat162 l23 = __floats2bfloat162_rn(v.z - __low2float(h23), v.w - __high2float(h23));
    ((uint2*)dh)[i] = make_uint2(*(uint32_t*)&h01, *(uint32_t*)&h23);
    ((uint2*)dl)[i] = make_uint2(*(uint32_t*)&l01, *(uint32_t*)&l23);
}

// ---- gemm smem layout (bytes) ----
#define SA_STR 72
#define SB_STR 136
#define SA_H   0                        // A hi: 256*72*2 = 36864
#define SA_L   36864                    // A lo
#define SB_BASE 73728                   // 2 sets x (hi 17408 + lo 17408)
#define SB_SET 34816
#define GEMM_SMEM 143360
#define SC_STR 132                      // fp32 bounce: 256*132*4 = 135168 (aliases)

// ============================================================================
// C[M,Ntot] = (Ah+Al)[M,384] * (Bh+Bl)[384,Ntot] (+bias)
// CTA tile 256x128, 8 warps, warp tile 64x64 (MMA:LDSM = 3:1).
// grid=(M/256, Ntot/128), block=256. cp.async, B double-buffered.
// ============================================================================
__global__ void __launch_bounds__(256, 1)
gemm_bf16(const __nv_bfloat16* __restrict__ Ah, const __nv_bfloat16* __restrict__ Al,
          const __nv_bfloat16* __restrict__ Bh, const __nv_bfloat16* __restrict__ Bl,
          const float* __restrict__ bias, float* __restrict__ C, int Ntot)
{
    extern __shared__ char smc[];
    const int tid = threadIdx.x, wid = tid >> 5;
    const long m0 = (long)blockIdx.x * 256;
    const int n0 = blockIdx.y * 128;
    const int wm = wid & 3;             // 4 x 64 rows
    const int wn = wid >> 2;            // 2 x 64 cols
    const uint32_t sbase = s2u(smc);

    wmma::fragment<wmma::accumulator, 16, 16, 16, float> acc[4][4];
#pragma unroll
    for (int i = 0; i < 4; i++)
#pragma unroll
        for (int j = 0; j < 4; j++) wmma::fill_fragment(acc[i][j], 0.0f);

    auto stageB = [&](int kc, int bi) {
        uint32_t sbh = sbase + SB_BASE + bi * SB_SET;
        uint32_t sbl = sbh + 17408;
#pragma unroll
        for (int i = 0; i < 4; i++) {
            int e = i * 256 + tid;              // 0..1023
            int k = e >> 4, c8 = e & 15;
            long go = (long)(kc * 64 + k) * Ntot + n0 + c8 * 8;
            uint32_t so = (uint32_t)(k * SB_STR + c8 * 8) * 2;
            cpa16(sbh + so, Bh + go);
            cpa16(sbl + so, Bl + go);
        }
        asm volatile("cp.async.commit_group;");
    };

    stageB(0, 0);

    for (int kc = 0; kc < 6; kc++) {
        const int bi = kc & 1;
        // ---- stage A chunk kc: 256 rows x 64 k, hi+lo ----
#pragma unroll
        for (int i = 0; i < 8; i++) {
            int e = i * 256 + tid;              // 0..2047
            int r = e >> 3, c8 = e & 7;
            long go = (m0 + r) * 384 + kc * 64 + c8 * 8;
            uint32_t so = (uint32_t)(r * SA_STR + c8 * 8) * 2;
            cpa16(sbase + SA_H + so, Ah + go);
            cpa16(sbase + SA_L + so, Al + go);
        }
        asm volatile("cp.async.commit_group;");
        if (kc < 5) {
            stageB(kc + 1, bi ^ 1);
            asm volatile("cp.async.wait_group 1;");   // A(kc)+B(kc) done
        } else {
            asm volatile("cp.async.wait_group 0;");
        }
        __syncthreads();

        const __nv_bfloat16* bAh = (const __nv_bfloat16*)(smc + SA_H);
        const __nv_bfloat16* bAl = (const __nv_bfloat16*)(smc + SA_L);
        const __nv_bfloat16* bBh = (const __nv_bfloat16*)(smc + SB_BASE + bi * SB_SET);
        const __nv_bfloat16* bBl = (const __nv_bfloat16*)(smc + SB_BASE + bi * SB_SET + 17408);
#pragma unroll
        for (int k16 = 0; k16 < 4; k16++) {
            // register-cache all 8 B fragments for this k16
            wmma::fragment<wmma::matrix_b, 16, 16, 16, __nv_bfloat16, wmma::row_major> bh[4], bl[4];
#pragma unroll
            for (int j = 0; j < 4; j++) {
                wmma::load_matrix_sync(bh[j], &bBh[(k16 * 16) * SB_STR + wn * 64 + j * 16], SB_STR);
                wmma::load_matrix_sync(bl[j], &bBl[(k16 * 16) * SB_STR + wn * 64 + j * 16], SB_STR);
            }
#pragma unroll
            for (int i = 0; i < 4; i++) {
                wmma::fragment<wmma::matrix_a, 16, 16, 16, __nv_bfloat16, wmma::row_major> ah, al;
                wmma::load_matrix_sync(ah, &bAh[(wm * 64 + i * 16) * SA_STR + k16 * 16], SA_STR);
                wmma::load_matrix_sync(al, &bAl[(wm * 64 + i * 16) * SA_STR + k16 * 16], SA_STR);
#pragma unroll
                for (int j = 0; j < 4; j++) {
                    wmma::mma_sync(acc[i][j], ah, bh[j], acc[i][j]);
                    wmma::mma_sync(acc[i][j], ah, bl[j], acc[i][j]);
                    wmma::mma_sync(acc[i][j], al, bh[j], acc[i][j]);
                }
            }
        }
        __syncthreads();
    }

    // ---- epilogue: frags -> smem bounce -> bias + coalesced fp32 store ----
    float* sC = (float*)smc;
#pragma unroll
    for (int i = 0; i < 4; i++)
#pragma unroll
        for (int j = 0; j < 4; j++)
            wmma::store_matrix_sync(&sC[(wm * 64 + i * 16) * SC_STR + wn * 64 + j * 16],
                                    acc[i][j], SC_STR, wmma::mem_row_major);
    __syncthreads();
#pragma unroll
    for (int i = 0; i < 32; i++) {
        int e = i * 256 + tid;                  // float4 idx over 256x128
        int r = e >> 5, c4 = e & 31;
        float4 v = *(const float4*)&sC[r * SC_STR + c4 * 4];
        if (bias) {
            float4 bv = *(const float4*)&bias[n0 + c4 * 4];
            v.x += bv.x; v.y += bv.y; v.z += bv.z; v.w += bv.w;
        }
        *(float4*)&C[(m0 + r) * Ntot + n0 + c4 * 4] = v;
    }
}

// ============================================================================
// K2: register-tiled windowed attention, 4 heads in flight (unchanged R13)
// ============================================================================
#define HS 2308
#define SQ_OFF 0
#define SK_OFF 9232
#define SV_OFF 18464
#define PS_OFF 27696
#define ATTN_SMEM_FLOATS 45104

__global__ void __launch_bounds__(512, 1)
attn_win()
{
    extern __shared__ float sm[];
    const int tid = threadIdx.x;
    const int n = blockIdx.x;
    const int b = n >> 6, ih = (n >> 3) & 7, iw = n & 7;
    const int tb = (b * 64 + ih * 8) * 64 + iw * 8;

    const int hq = tid >> 7;
    const int st = tid & 127;
    const int rg = st >> 3;
    const int cg8 = st & 7;
    const int r0 = rg * 4;
    const int rql = st >> 2;
    const int dq = st & 3;

    for (int hp = 0; hp < 3; hp++) {
        const int h0 = hp * 4;
        __syncthreads();
#pragma unroll
        for (int i = 0; i < 12; i++) {
            int e = i * 512 + tid;
            int c8 = e & 7;
            int r = e >> 3;
            int hh4 = r & 3; r >>= 2;
            int p = r % 3;
            int t = r / 3;
            long gf4 = (long)(tb + (t >> 3) * 64 + (t & 7)) * 288 + p * 96 + (h0 + hh4) * 8 + c8;
            float4 v = ((const float4*)g_qkv)[gf4];
            int base = (p == 0) ? SQ_OFF : (p == 1 ? SK_OFF : SV_OFF);
            if (p == 0) { v.x *= SCALE; v.y *= SCALE; v.z *= SCALE; v.w *= SCALE; }
            *(float4*)&sm[base + hh4 * HS + t * 36 + c8 * 4] = v;
        }
        __syncthreads();

        float acc[4][8];
#pragma unroll
        for (int i = 0; i < 4; i++)
#pragma unroll
            for (int j = 0; j < 8; j++) acc[i][j] = 0.f;

        const float* qb = &sm[SQ_OFF + hq * HS];
        const float* kb = &sm[SK_OFF + hq * HS];
#pragma unroll
        for (int dblk = 0; dblk < 8; dblk++) {
            float4 qv[4];
#pragma unroll
            for (int i = 0; i < 4; i++)
                qv[i] = *(const float4*)&qb[(r0 + i) * 36 + dblk * 4];
#pragma unroll
            for (int j = 0; j < 8; j++) {
                float4 kv = *(const float4*)&kb[(j * 8 + cg8) * 36 + dblk * 4];
#pragma unroll
                for (int i = 0; i < 4; i++) {
                    acc[i][j] = fmaf(qv[i].x, kv.x, acc[i][j]);
                    acc[i][j] = fmaf(qv[i].y, kv.y, acc[i][j]);
                    acc[i][j] = fmaf(qv[i].z, kv.z, acc[i][j]);
                    acc[i][j] = fmaf(qv[i].w, kv.w, acc[i][j]);
                }
            }
        }

        float* psb = &sm[PS_OFF + hq * 4352];
#pragma unroll
        for (int i = 0; i < 4; i++) {
            float m = acc[i][0];
#pragma unroll
            for (int j = 1; j < 8; j++) m = fmaxf(m, acc[i][j]);
            m = fmaxf(m, __shfl_xor_sync(0xffffffffu, m, 1));
            m = fmaxf(m, __shfl_xor_sync(0xffffffffu, m, 2));
            m = fmaxf(m, __shfl_xor_sync(0xffffffffu, m, 4));
            float s = 0.f;
#pragma unroll
            for (int j = 0; j < 8; j++) { acc[i][j] = __expf(acc[i][j] - m); s += acc[i][j]; }
            s += __shfl_xor_sync(0xffffffffu, s, 1);
            s += __shfl_xor_sync(0xffffffffu, s, 2);
            s += __shfl_xor_sync(0xffffffffu, s, 4);
            float inv = 1.f / s;
#pragma unroll
            for (int j = 0; j < 8; j++)
                psb[(r0 + i) * 68 + j * 8 + cg8] = acc[i][j] * inv;
        }
        __syncthreads();

        ull oa[2][4];
#pragma unroll
        for (int i = 0; i < 2; i++)
#pragma unroll
            for (int j = 0; j < 4; j++) oa[i][j] = 0ull;

        const float* vb = &sm[SV_OFF + hq * HS + dq * 8];
        const float* p0 = &sm[PS_OFF + hq * 4352 + (rql * 2) * 68];
        const float* p1 = p0 + 68;
#pragma unroll 8
        for (int j = 0; j < 64; j++) {
            ulonglong2 va = *(const ulonglong2*)(vb + j * 36);
            ulonglong2 vc = *(const ulonglong2*)(vb + j * 36 + 4);
            ull P0 = pk2(p0[j], p0[j]);
            ull P1 = pk2(p1[j], p1[j]);
            ffma2(oa[0][0], P0, va.x); ffma2(oa[0][1], P0, va.y);
            ffma2(oa[0][2], P0, vc.x); ffma2(oa[0][3], P0, vc.y);
            ffma2(oa[1][0], P1, va.x); ffma2(oa[1][1], P1, va.y);
            ffma2(oa[1][2], P1, vc.x); ffma2(oa[1][3], P1, vc.y);
        }
#pragma unroll
        for (int i = 0; i < 2; i++) {
            int row = rql * 2 + i;
            long gtok = tb + (row >> 3) * 64 + (row & 7);
            long go = gtok * 384 + (h0 + hq) * 32 + dq * 8;
            float o[8];
            upk2(oa[i][0], o[0], o[1]); upk2(oa[i][1], o[2], o[3]);
            upk2(oa[i][2], o[4], o[5]); upk2(oa[i][3], o[6], o[7]);
            uint32_t hw[4], lw[4];
#pragma unroll
            for (int q2 = 0; q2 < 4; q2++) {
                __nv_bfloat162 h2 = __floats2bfloat162_rn(o[2 * q2], o[2 * q2 + 1]);
                __nv_bfloat162 l2 = __floats2bfloat162_rn(o[2 * q2] - __low2float(h2),
                                                          o[2 * q2 + 1] - __high2float(h2));
                hw[q2] = *(uint32_t*)&h2;
                lw[q2] = *(uint32_t*)&l2;
            }
            *(uint4*)&g_aoh[go] = make_uint4(hw[0], hw[1], hw[2], hw[3]);
            *(uint4*)&g_aol[go] = make_uint4(lw[0], lw[1], lw[2], lw[3]);
        }
    }
}

// ============================================================================
extern "C" void kernel_launch(void* const* d_in, const int* in_sizes, int n_in,
                              void* d_out, int out_size)
{
    const float* x    = (const float*)d_in[0];
    const float* wqkv = (const float*)d_in[1];
    const float* wout = (const float*)d_in[2];
    const float* bout = (const float*)d_in[3];
    float* out = (float*)d_out;

    static float* p_qkv = nullptr;
    static __nv_bfloat16 *p_aoh, *p_aol, *p_wqh, *p_wql, *p_woh, *p_wol;
    if (!p_qkv) {
        cudaGetSymbolAddress((void**)&p_qkv, g_qkv);
        cudaGetSymbolAddress((void**)&p_aoh, g_aoh);
        cudaGetSymbolAddress((void**)&p_aol, g_aol);
        cudaGetSymbolAddress((void**)&p_wqh, g_wqh);
        cudaGetSymbolAddress((void**)&p_wql, g_wql);
        cudaGetSymbolAddress((void**)&p_woh, g_woh);
        cudaGetSymbolAddress((void**)&p_wol, g_wol);
        cudaFuncSetAttribute(gemm_bf16,
                             cudaFuncAttributeMaxDynamicSharedMemorySize, GEMM_SMEM);
        cudaFuncSetAttribute(attn_win,
                             cudaFuncAttributeMaxDynamicSharedMemorySize,
                             ATTN_SMEM_FLOATS * sizeof(float));
    }

    // x -> bf16 hi/lo staged in g_aoh/g_aol (dead until attn_win rewrites them)
    conv_hilo<<<12582912 / 256, 256>>>(x, p_aoh, p_aol, 12582912);
    conv_hilo<<<110592 / 256, 256>>>(wqkv, p_wqh, p_wql, 110592);
    conv_hilo<<<36864 / 256, 256>>>(wout, p_woh, p_wol, 36864);

    dim3 g1(512, 9), g3(512, 3);
    gemm_bf16<<<g1, 256, GEMM_SMEM>>>(p_aoh, p_aol, p_wqh, p_wql, nullptr, p_qkv, 1152);
    attn_win<<<2048, 512, ATTN_SMEM_FLOATS * sizeof(float)>>>();
    gemm_bf16<<<g3, 256, GEMM_SMEM>>>(p_aoh, p_aol, p_woh, p_wol, bout, out, 384);
}

// round 16
// speedup vs baseline: 3.8771x; 1.0002x over previous
#include <cuda_runtime.h>
#include <cuda_bf16.h>
#include <mma.h>
#include <cstdint>

using namespace nvcuda;
typedef unsigned long long ull;

#define SCALE 0.17677669529663687f

// ---- persistent scratch (device statics, ~807 MB) ----
__device__ float g_qkv[150994944];              // [131072][1152] fp32
__device__ __nv_bfloat16 g_aoh[50331648];       // x-hi (K1 input) then attn-out hi
__device__ __nv_bfloat16 g_aol[50331648];       // x-lo (K1 input) then attn-out lo
__device__ __nv_bfloat16 g_wqh[442368];         // w_qkv hi/lo [384][1152]
__device__ __nv_bfloat16 g_wql[442368];
__device__ __nv_bfloat16 g_woh[147456];         // w_out hi/lo [384][384]
__device__ __nv_bfloat16 g_wol[147456];

__device__ __forceinline__ uint32_t s2u(const void* p) {
    uint32_t a;
    asm("{ .reg .u64 t; cvta.to.shared.u64 t, %1; cvt.u32.u64 %0, t; }" : "=r"(a) : "l"(p));
    return a;
}
__device__ __forceinline__ void cpa16(uint32_t dst, const void* src) {
    asm volatile("cp.async.ca.shared.global [%0], [%1], 16;" :: "r"(dst), "l"(src));
}
__device__ __forceinline__ ull pk2(float lo, float hi) {
    ull r; asm("mov.b64 %0,{%1,%2};" : "=l"(r) : "f"(lo), "f"(hi)); return r;
}
__device__ __forceinline__ void upk2(ull v, float &lo, float &hi) {
    asm("mov.b64 {%0,%1},%2;" : "=f"(lo), "=f"(hi) : "l"(v));
}
__device__ __forceinline__ void ffma2(ull &d, ull a, ull b) {
    asm("fma.rn.f32x2 %0,%1,%2,%0;" : "+l"(d) : "l"(a), "l"(b));
}

// ============================================================================
// prep: fp32 -> bf16 hi/lo
// ============================================================================
__global__ void conv_hilo(const float* __restrict__ src, __nv_bfloat16* __restrict__ dh,
                          __nv_bfloat16* __restrict__ dl, int n4)
{
    int i = blockIdx.x * blockDim.x + threadIdx.x;
    if (i >= n4) return;
    float4 v = ((const float4*)src)[i];
    __nv_bfloat162 h01 = __floats2bfloat162_rn(v.x, v.y);
    __nv_bfloat162 h23 = __floats2bfloat162_rn(v.z, v.w);
    __nv_bfloat162 l01 = __floats2bfloat162_rn(v.x - __low2float(h01), v.y - __high2float(h01));
    __nv_bfloat162 l23 = __floats2bfloat162_rn(v.z - __low2float(h23), v.w - __high2float(h23));
    ((uint2*)dh)[i] = make_uint2(*(uint32_t*)&h01, *(uint32_t*)&h23);
    ((uint2*)dl)[i] = make_uint2(*(uint32_t*)&l01, *(uint32_t*)&l23);
}

// ---- gemm smem layout (bytes) ----
#define SA_STR 72
#define SB_STR 136
#define SA_H   0                        // A hi: 256*72*2 = 36864
#define SA_L   36864
#define SB_BASE 73728                   // 2 sets x (hi 17408 + lo 17408)
#define SB_SET 34816
#define GEMM_SMEM 143360
#define SC_STR 132                      // fp32 bounce: 256*132*4 = 135168 (aliases)

// ============================================================================
// C[M,Ntot] = (Ah+Al)[M,384] * (Bh+Bl)[384,Ntot] (+bias)
// CTA tile 256x128, 512 threads / 16 warps, warp tile 64x32.
// acc[4][2]=64 regs/thread + cached B (16) + streamed A (8) => no spill.
// grid=(M/256, Ntot/128). cp.async, B double-buffered.
// ============================================================================
__global__ void __launch_bounds__(512, 1)
gemm_bf16(const __nv_bfloat16* __restrict__ Ah, const __nv_bfloat16* __restrict__ Al,
          const __nv_bfloat16* __restrict__ Bh, const __nv_bfloat16* __restrict__ Bl,
          const float* __restrict__ bias, float* __restrict__ C, int Ntot)
{
    extern __shared__ char smc[];
    const int tid = threadIdx.x, wid = tid >> 5;
    const long m0 = (long)blockIdx.x * 256;
    const int n0 = blockIdx.y * 128;
    const int wm = wid & 3;             // 4 x 64 rows
    const int wn = wid >> 2;            // 4 x 32 cols
    const uint32_t sbase = s2u(smc);

    wmma::fragment<wmma::accumulator, 16, 16, 16, float> acc[4][2];
#pragma unroll
    for (int i = 0; i < 4; i++)
#pragma unroll
        for (int j = 0; j < 2; j++) wmma::fill_fragment(acc[i][j], 0.0f);

    auto stageB = [&](int kc, int bi) {
        uint32_t sbh = sbase + SB_BASE + bi * SB_SET;
        uint32_t sbl = sbh + 17408;
#pragma unroll
        for (int i = 0; i < 2; i++) {
            int e = i * 512 + tid;              // 0..1023
            int k = e >> 4, c8 = e & 15;
            long go = (long)(kc * 64 + k) * Ntot + n0 + c8 * 8;
            uint32_t so = (uint32_t)(k * SB_STR + c8 * 8) * 2;
            cpa16(sbh + so, Bh + go);
            cpa16(sbl + so, Bl + go);
        }
        asm volatile("cp.async.commit_group;");
    };

    stageB(0, 0);

    for (int kc = 0; kc < 6; kc++) {
        const int bi = kc & 1;
        // ---- stage A chunk kc: 256 rows x 64 k, hi+lo ----
#pragma unroll
        for (int i = 0; i < 4; i++) {
            int e = i * 512 + tid;              // 0..2047
            int r = e >> 3, c8 = e & 7;
            long go = (m0 + r) * 384 + kc * 64 + c8 * 8;
            uint32_t so = (uint32_t)(r * SA_STR + c8 * 8) * 2;
            cpa16(sbase + SA_H + so, Ah + go);
            cpa16(sbase + SA_L + so, Al + go);
        }
        asm volatile("cp.async.commit_group;");
        if (kc < 5) {
            stageB(kc + 1, bi ^ 1);
            asm volatile("cp.async.wait_group 1;");   // A(kc)+B(kc) done
        } else {
            asm volatile("cp.async.wait_group 0;");
        }
        __syncthreads();

        const __nv_bfloat16* bAh = (const __nv_bfloat16*)(smc + SA_H);
        const __nv_bfloat16* bAl = (const __nv_bfloat16*)(smc + SA_L);
        const __nv_bfloat16* bBh = (const __nv_bfloat16*)(smc + SB_BASE + bi * SB_SET);
        const __nv_bfloat16* bBl = (const __nv_bfloat16*)(smc + SB_BASE + bi * SB_SET + 17408);
#pragma unroll
        for (int k16 = 0; k16 < 4; k16++) {
            // cache this warp's 4 B fragments for k16
            wmma::fragment<wmma::matrix_b, 16, 16, 16, __nv_bfloat16, wmma::row_major> bh[2], bl[2];
#pragma unroll
            for (int j = 0; j < 2; j++) {
                wmma::load_matrix_sync(bh[j], &bBh[(k16 * 16) * SB_STR + wn * 32 + j * 16], SB_STR);
                wmma::load_matrix_sync(bl[j], &bBl[(k16 * 16) * SB_STR + wn * 32 + j * 16], SB_STR);
            }
#pragma unroll
            for (int i = 0; i < 4; i++) {
                wmma::fragment<wmma::matrix_a, 16, 16, 16, __nv_bfloat16, wmma::row_major> ah, al;
                wmma::load_matrix_sync(ah, &bAh[(wm * 64 + i * 16) * SA_STR + k16 * 16], SA_STR);
                wmma::load_matrix_sync(al, &bAl[(wm * 64 + i * 16) * SA_STR + k16 * 16], SA_STR);
#pragma unroll
                for (int j = 0; j < 2; j++) {
                    wmma::mma_sync(acc[i][j], ah, bh[j], acc[i][j]);
                    wmma::mma_sync(acc[i][j], ah, bl[j], acc[i][j]);
                    wmma::mma_sync(acc[i][j], al, bh[j], acc[i][j]);
                }
            }
        }
        __syncthreads();
    }

    // ---- epilogue: frags -> smem bounce -> bias + coalesced fp32 store ----
    float* sC = (float*)smc;
#pragma unroll
    for (int i = 0; i < 4; i++)
#pragma unroll
        for (int j = 0; j < 2; j++)
            wmma::store_matrix_sync(&sC[(wm * 64 + i * 16) * SC_STR + wn * 32 + j * 16],
                                    acc[i][j], SC_STR, wmma::mem_row_major);
    __syncthreads();
#pragma unroll
    for (int i = 0; i < 16; i++) {
        int e = i * 512 + tid;                  // float4 idx over 256x128
        int r = e >> 5, c4 = e & 31;
        float4 v = *(const float4*)&sC[r * SC_STR + c4 * 4];
        if (bias) {
            float4 bv = *(const float4*)&bias[n0 + c4 * 4];
            v.x += bv.x; v.y += bv.y; v.z += bv.z; v.w += bv.w;
        }
        *(float4*)&C[(m0 + r) * Ntot + n0 + c4 * 4] = v;
    }
}

// ============================================================================
// K2: register-tiled windowed attention, 4 heads in flight (unchanged R13)
// ============================================================================
#define HS 2308
#define SQ_OFF 0
#define SK_OFF 9232
#define SV_OFF 18464
#define PS_OFF 27696
#define ATTN_SMEM_FLOATS 45104

__global__ void __launch_bounds__(512, 1)
attn_win()
{
    extern __shared__ float sm[];
    const int tid = threadIdx.x;
    const int n = blockIdx.x;
    const int b = n >> 6, ih = (n >> 3) & 7, iw = n & 7;
    const int tb = (b * 64 + ih * 8) * 64 + iw * 8;

    const int hq = tid >> 7;
    const int st = tid & 127;
    const int rg = st >> 3;
    const int cg8 = st & 7;
    const int r0 = rg * 4;
    const int rql = st >> 2;
    const int dq = st & 3;

    for (int hp = 0; hp < 3; hp++) {
        const int h0 = hp * 4;
        __syncthreads();
#pragma unroll
        for (int i = 0; i < 12; i++) {
            int e = i * 512 + tid;
            int c8 = e & 7;
            int r = e >> 3;
            int hh4 = r & 3; r >>= 2;
            int p = r % 3;
            int t = r / 3;
            long gf4 = (long)(tb + (t >> 3) * 64 + (t & 7)) * 288 + p * 96 + (h0 + hh4) * 8 + c8;
            float4 v = ((const float4*)g_qkv)[gf4];
            int base = (p == 0) ? SQ_OFF : (p == 1 ? SK_OFF : SV_OFF);
            if (p == 0) { v.x *= SCALE; v.y *= SCALE; v.z *= SCALE; v.w *= SCALE; }
            *(float4*)&sm[base + hh4 * HS + t * 36 + c8 * 4] = v;
        }
        __syncthreads();

        float acc[4][8];
#pragma unroll
        for (int i = 0; i < 4; i++)
#pragma unroll
            for (int j = 0; j < 8; j++) acc[i][j] = 0.f;

        const float* qb = &sm[SQ_OFF + hq * HS];
        const float* kb = &sm[SK_OFF + hq * HS];
#pragma unroll
        for (int dblk = 0; dblk < 8; dblk++) {
            float4 qv[4];
#pragma unroll
            for (int i = 0; i < 4; i++)
                qv[i] = *(const float4*)&qb[(r0 + i) * 36 + dblk * 4];
#pragma unroll
            for (int j = 0; j < 8; j++) {
                float4 kv = *(const float4*)&kb[(j * 8 + cg8) * 36 + dblk * 4];
#pragma unroll
                for (int i = 0; i < 4; i++) {
                    acc[i][j] = fmaf(qv[i].x, kv.x, acc[i][j]);
                    acc[i][j] = fmaf(qv[i].y, kv.y, acc[i][j]);
                    acc[i][j] = fmaf(qv[i].z, kv.z, acc[i][j]);
                    acc[i][j] = fmaf(qv[i].w, kv.w, acc[i][j]);
                }
            }
        }

        float* psb = &sm[PS_OFF + hq * 4352];
#pragma unroll
        for (int i = 0; i < 4; i++) {
            float m = acc[i][0];
#pragma unroll
            for (int j = 1; j < 8; j++) m = fmaxf(m, acc[i][j]);
            m = fmaxf(m, __shfl_xor_sync(0xffffffffu, m, 1));
            m = fmaxf(m, __shfl_xor_sync(0xffffffffu, m, 2));
            m = fmaxf(m, __shfl_xor_sync(0xffffffffu, m, 4));
            float s = 0.f;
#pragma unroll
            for (int j = 0; j < 8; j++) { acc[i][j] = __expf(acc[i][j] - m); s += acc[i][j]; }
            s += __shfl_xor_sync(0xffffffffu, s, 1);
            s += __shfl_xor_sync(0xffffffffu, s, 2);
            s += __shfl_xor_sync(0xffffffffu, s, 4);
            float inv = 1.f / s;
#pragma unroll
            for (int j = 0; j < 8; j++)
                psb[(r0 + i) * 68 + j * 8 + cg8] = acc[i][j] * inv;
        }
        __syncthreads();

        ull oa[2][4];
#pragma unroll
        for (int i = 0; i < 2; i++)
#pragma unroll
            for (int j = 0; j < 4; j++) oa[i][j] = 0ull;

        const float* vb = &sm[SV_OFF + hq * HS + dq * 8];
        const float* p0 = &sm[PS_OFF + hq * 4352 + (rql * 2) * 68];
        const float* p1 = p0 + 68;
#pragma unroll 8
        for (int j = 0; j < 64; j++) {
            ulonglong2 va = *(const ulonglong2*)(vb + j * 36);
            ulonglong2 vc = *(const ulonglong2*)(vb + j * 36 + 4);
            ull P0 = pk2(p0[j], p0[j]);
            ull P1 = pk2(p1[j], p1[j]);
            ffma2(oa[0][0], P0, va.x); ffma2(oa[0][1], P0, va.y);
            ffma2(oa[0][2], P0, vc.x); ffma2(oa[0][3], P0, vc.y);
            ffma2(oa[1][0], P1, va.x); ffma2(oa[1][1], P1, va.y);
            ffma2(oa[1][2], P1, vc.x); ffma2(oa[1][3], P1, vc.y);
        }
#pragma unroll
        for (int i = 0; i < 2; i++) {
            int row = rql * 2 + i;
            long gtok = tb + (row >> 3) * 64 + (row & 7);
            long go = gtok * 384 + (h0 + hq) * 32 + dq * 8;
            float o[8];
            upk2(oa[i][0], o[0], o[1]); upk2(oa[i][1], o[2], o[3]);
            upk2(oa[i][2], o[4], o[5]); upk2(oa[i][3], o[6], o[7]);
            uint32_t hw[4], lw[4];
#pragma unroll
            for (int q2 = 0; q2 < 4; q2++) {
                __nv_bfloat162 h2 = __floats2bfloat162_rn(o[2 * q2], o[2 * q2 + 1]);
                __nv_bfloat162 l2 = __floats2bfloat162_rn(o[2 * q2] - __low2float(h2),
                                                          o[2 * q2 + 1] - __high2float(h2));
                hw[q2] = *(uint32_t*)&h2;
                lw[q2] = *(uint32_t*)&l2;
            }
            *(uint4*)&g_aoh[go] = make_uint4(hw[0], hw[1], hw[2], hw[3]);
            *(uint4*)&g_aol[go] = make_uint4(lw[0], lw[1], lw[2], lw[3]);
        }
    }
}

// ============================================================================
extern "C" void kernel_launch(void* const* d_in, const int* in_sizes, int n_in,
                              void* d_out, int out_size)
{
    const float* x    = (const float*)d_in[0];
    const float* wqkv = (const float*)d_in[1];
    const float* wout = (const float*)d_in[2];
    const float* bout = (const float*)d_in[3];
    float* out = (float*)d_out;

    static float* p_qkv = nullptr;
    static __nv_bfloat16 *p_aoh, *p_aol, *p_wqh, *p_wql, *p_woh, *p_wol;
    if (!p_qkv) {
        cudaGetSymbolAddress((void**)&p_qkv, g_qkv);
        cudaGetSymbolAddress((void**)&p_aoh, g_aoh);
        cudaGetSymbolAddress((void**)&p_aol, g_aol);
        cudaGetSymbolAddress((void**)&p_wqh, g_wqh);
        cudaGetSymbolAddress((void**)&p_wql, g_wql);
        cudaGetSymbolAddress((void**)&p_woh, g_woh);
        cudaGetSymbolAddress((void**)&p_wol, g_wol);
        cudaFuncSetAttribute(gemm_bf16,
                             cudaFuncAttributeMaxDynamicSharedMemorySize, GEMM_SMEM);
        cudaFuncSetAttribute(attn_win,
                             cudaFuncAttributeMaxDynamicSharedMemorySize,
                             ATTN_SMEM_FLOATS * sizeof(float));
    }

    // x -> bf16 hi/lo staged in g_aoh/g_aol (dead until attn_win rewrites them)
    conv_hilo<<<12582912 / 256, 256>>>(x, p_aoh, p_aol, 12582912);
    conv_hilo<<<110592 / 256, 256>>>(wqkv, p_wqh, p_wql, 110592);
    conv_hilo<<<36864 / 256, 256>>>(wout, p_woh, p_wol, 36864);

    dim3 g1(512, 9), g3(512, 3);
    gemm_bf16<<<g1, 512, GEMM_SMEM>>>(p_aoh, p_aol, p_wqh, p_wql, nullptr, p_qkv, 1152);
    attn_win<<<2048, 512, ATTN_SMEM_FLOATS * sizeof(float)>>>();
    gemm_bf16<<<g3, 512, GEMM_SMEM>>>(p_aoh, p_aol, p_woh, p_wol, bout, out, 384);
}

// round 17
// speedup vs baseline: 4.6222x; 1.1922x over previous
#include <cuda_runtime.h>
#include <cuda_bf16.h>
#include <cuda_fp16.h>
#include <mma.h>
#include <cstdint>

using namespace nvcuda;
typedef unsigned long long ull;

#define SCALE 0.17677669529663687f

// ---- persistent scratch (device statics, ~807 MB) ----
__device__ float g_qkv[150994944];              // [131072][1152] fp32
__device__ __nv_bfloat16 g_aoh[50331648];       // x-hi fp16 (K1) then attn-out hi bf16 (K3)
__device__ __nv_bfloat16 g_aol[50331648];       // x-lo fp16 (K1) then attn-out lo bf16 (K3)
__device__ __nv_bfloat16 g_wqh[442368];         // w_qkv fp16 single [384][1152]
__device__ __nv_bfloat16 g_wql[442368];         // (unused this round)
__device__ __nv_bfloat16 g_woh[147456];         // w_out bf16 hi/lo [384][384]
__device__ __nv_bfloat16 g_wol[147456];

__device__ __forceinline__ uint32_t s2u(const void* p) {
    uint32_t a;
    asm("{ .reg .u64 t; cvta.to.shared.u64 t, %1; cvt.u32.u64 %0, t; }" : "=r"(a) : "l"(p));
    return a;
}
__device__ __forceinline__ void cpa16(uint32_t dst, const void* src) {
    asm volatile("cp.async.ca.shared.global [%0], [%1], 16;" :: "r"(dst), "l"(src));
}
__device__ __forceinline__ ull pk2(float lo, float hi) {
    ull r; asm("mov.b64 %0,{%1,%2};" : "=l"(r) : "f"(lo), "f"(hi)); return r;
}
__device__ __forceinline__ void upk2(ull v, float &lo, float &hi) {
    asm("mov.b64 {%0,%1},%2;" : "=f"(lo), "=f"(hi) : "l"(v));
}
__device__ __forceinline__ void ffma2(ull &d, ull a, ull b) {
    asm("fma.rn.f32x2 %0,%1,%2,%0;" : "+l"(d) : "l"(a), "l"(b));
}

// ============================================================================
// prep kernels
// ============================================================================
__global__ void conv_f16_hilo(const float* __restrict__ src, __half* __restrict__ dh,
                              __half* __restrict__ dl, int n4)
{
    int i = blockIdx.x * blockDim.x + threadIdx.x;
    if (i >= n4) return;
    float4 v = ((const float4*)src)[i];
    __half2 h01 = __floats2half2_rn(v.x, v.y);
    __half2 h23 = __floats2half2_rn(v.z, v.w);
    __half2 l01 = __floats2half2_rn(v.x - __low2float(h01), v.y - __high2float(h01));
    __half2 l23 = __floats2half2_rn(v.z - __low2float(h23), v.w - __high2float(h23));
    ((uint2*)dh)[i] = make_uint2(*(uint32_t*)&h01, *(uint32_t*)&h23);
    ((uint2*)dl)[i] = make_uint2(*(uint32_t*)&l01, *(uint32_t*)&l23);
}

__global__ void conv_f16(const float* __restrict__ src, __half* __restrict__ dh, int n4)
{
    int i = blockIdx.x * blockDim.x + threadIdx.x;
    if (i >= n4) return;
    float4 v = ((const float4*)src)[i];
    __half2 h01 = __floats2half2_rn(v.x, v.y);
    __half2 h23 = __floats2half2_rn(v.z, v.w);
    ((uint2*)dh)[i] = make_uint2(*(uint32_t*)&h01, *(uint32_t*)&h23);
}

__global__ void conv_hilo(const float* __restrict__ src, __nv_bfloat16* __restrict__ dh,
                          __nv_bfloat16* __restrict__ dl, int n4)
{
    int i = blockIdx.x * blockDim.x + threadIdx.x;
    if (i >= n4) return;
    float4 v = ((const float4*)src)[i];
    __nv_bfloat162 h01 = __floats2bfloat162_rn(v.x, v.y);
    __nv_bfloat162 h23 = __floats2bfloat162_rn(v.z, v.w);
    __nv_bfloat162 l01 = __floats2bfloat162_rn(v.x - __low2float(h01), v.y - __high2float(h01));
    __nv_bfloat162 l23 = __floats2bfloat162_rn(v.z - __low2float(h23), v.w - __high2float(h23));
    ((uint2*)dh)[i] = make_uint2(*(uint32_t*)&h01, *(uint32_t*)&h23);
    ((uint2*)dl)[i] = make_uint2(*(uint32_t*)&l01, *(uint32_t*)&l23);
}

// ---- shared layouts (bytes) ----
#define SA_STR 72
#define SB_STR 136
#define SC_STR 132

// fp16 kernel: A hi/lo (36864 each), B single double-buffered (17408 each)
#define F16_SA_H 0
#define F16_SA_L 36864
#define F16_SB   73728
#define F16_SMEM 135168                 // fp32 bounce needs 256*132*4

// bf16 kernel (R16 layout)
#define B16_SA_H 0
#define B16_SA_L 36864
#define B16_SB   73728
#define B16_SET  34816
#define B16_SMEM 143360

// ============================================================================
// K1: C[M,1152] = (Ah+Al)fp16[M,384] * Bfp16[384,1152]   (2 MMAs per tile)
// CTA tile 256x128, 512 threads, warp tile 64x32.
// ============================================================================
__global__ void __launch_bounds__(512, 1)
gemm_f16_2m(const __half* __restrict__ Ah, const __half* __restrict__ Al,
            const __half* __restrict__ Bh, float* __restrict__ C, int Ntot)
{
    extern __shared__ char smc[];
    const int tid = threadIdx.x, wid = tid >> 5;
    const long m0 = (long)blockIdx.x * 256;
    const int n0 = blockIdx.y * 128;
    const int wm = wid & 3, wn = wid >> 2;
    const uint32_t sbase = s2u(smc);

    wmma::fragment<wmma::accumulator, 16, 16, 16, float> acc[4][2];
#pragma unroll
    for (int i = 0; i < 4; i++)
#pragma unroll
        for (int j = 0; j < 2; j++) wmma::fill_fragment(acc[i][j], 0.0f);

    auto stageB = [&](int kc, int bi) {
        uint32_t sbh = sbase + F16_SB + bi * 17408;
#pragma unroll
        for (int i = 0; i < 2; i++) {
            int e = i * 512 + tid;
            int k = e >> 4, c8 = e & 15;
            long go = (long)(kc * 64 + k) * Ntot + n0 + c8 * 8;
            cpa16(sbh + (uint32_t)(k * SB_STR + c8 * 8) * 2, Bh + go);
        }
        asm volatile("cp.async.commit_group;");
    };

    stageB(0, 0);

    for (int kc = 0; kc < 6; kc++) {
        const int bi = kc & 1;
#pragma unroll
        for (int i = 0; i < 4; i++) {
            int e = i * 512 + tid;
            int r = e >> 3, c8 = e & 7;
            long go = (m0 + r) * 384 + kc * 64 + c8 * 8;
            uint32_t so = (uint32_t)(r * SA_STR + c8 * 8) * 2;
            cpa16(sbase + F16_SA_H + so, Ah + go);
            cpa16(sbase + F16_SA_L + so, Al + go);
        }
        asm volatile("cp.async.commit_group;");
        if (kc < 5) {
            stageB(kc + 1, bi ^ 1);
            asm volatile("cp.async.wait_group 1;");
        } else {
            asm volatile("cp.async.wait_group 0;");
        }
        __syncthreads();

        const __half* bAh = (const __half*)(smc + F16_SA_H);
        const __half* bAl = (const __half*)(smc + F16_SA_L);
        const __half* bB  = (const __half*)(smc + F16_SB + bi * 17408);
#pragma unroll
        for (int k16 = 0; k16 < 4; k16++) {
            wmma::fragment<wmma::matrix_b, 16, 16, 16, __half, wmma::row_major> bf[2];
#pragma unroll
            for (int j = 0; j < 2; j++)
                wmma::load_matrix_sync(bf[j], &bB[(k16 * 16) * SB_STR + wn * 32 + j * 16], SB_STR);
#pragma unroll
            for (int i = 0; i < 4; i++) {
                wmma::fragment<wmma::matrix_a, 16, 16, 16, __half, wmma::row_major> ah, al;
                wmma::load_matrix_sync(ah, &bAh[(wm * 64 + i * 16) * SA_STR + k16 * 16], SA_STR);
                wmma::load_matrix_sync(al, &bAl[(wm * 64 + i * 16) * SA_STR + k16 * 16], SA_STR);
#pragma unroll
                for (int j = 0; j < 2; j++) {
                    wmma::mma_sync(acc[i][j], ah, bf[j], acc[i][j]);
                    wmma::mma_sync(acc[i][j], al, bf[j], acc[i][j]);
                }
            }
        }
        __syncthreads();
    }

    float* sC = (float*)smc;
#pragma unroll
    for (int i = 0; i < 4; i++)
#pragma unroll
        for (int j = 0; j < 2; j++)
            wmma::store_matrix_sync(&sC[(wm * 64 + i * 16) * SC_STR + wn * 32 + j * 16],
                                    acc[i][j], SC_STR, wmma::mem_row_major);
    __syncthreads();
#pragma unroll
    for (int i = 0; i < 16; i++) {
        int e = i * 512 + tid;
        int r = e >> 5, c4 = e & 31;
        float4 v = *(const float4*)&sC[r * SC_STR + c4 * 4];
        *(float4*)&C[(m0 + r) * Ntot + n0 + c4 * 4] = v;
    }
}

// ============================================================================
// K3: bf16 3-MMA hi/lo GEMM (R16, unchanged)
// ============================================================================
__global__ void __launch_bounds__(512, 1)
gemm_bf16(const __nv_bfloat16* __restrict__ Ah, const __nv_bfloat16* __restrict__ Al,
          const __nv_bfloat16* __restrict__ Bh, const __nv_bfloat16* __restrict__ Bl,
          const float* __restrict__ bias, float* __restrict__ C, int Ntot)
{
    extern __shared__ char smc[];
    const int tid = threadIdx.x, wid = tid >> 5;
    const long m0 = (long)blockIdx.x * 256;
    const int n0 = blockIdx.y * 128;
    const int wm = wid & 3, wn = wid >> 2;
    const uint32_t sbase = s2u(smc);

    wmma::fragment<wmma::accumulator, 16, 16, 16, float> acc[4][2];
#pragma unroll
    for (int i = 0; i < 4; i++)
#pragma unroll
        for (int j = 0; j < 2; j++) wmma::fill_fragment(acc[i][j], 0.0f);

    auto stageB = [&](int kc, int bi) {
        uint32_t sbh = sbase + B16_SB + bi * B16_SET;
        uint32_t sbl = sbh + 17408;
#pragma unroll
        for (int i = 0; i < 2; i++) {
            int e = i * 512 + tid;
            int k = e >> 4, c8 = e & 15;
            long go = (long)(kc * 64 + k) * Ntot + n0 + c8 * 8;
            uint32_t so = (uint32_t)(k * SB_STR + c8 * 8) * 2;
            cpa16(sbh + so, Bh + go);
            cpa16(sbl + so, Bl + go);
        }
        asm volatile("cp.async.commit_group;");
    };

    stageB(0, 0);

    for (int kc = 0; kc < 6; kc++) {
        const int bi = kc & 1;
#pragma unroll
        for (int i = 0; i < 4; i++) {
            int e = i * 512 + tid;
            int r = e >> 3, c8 = e & 7;
            long go = (m0 + r) * 384 + kc * 64 + c8 * 8;
            uint32_t so = (uint32_t)(r * SA_STR + c8 * 8) * 2;
            cpa16(sbase + B16_SA_H + so, Ah + go);
            cpa16(sbase + B16_SA_L + so, Al + go);
        }
        asm volatile("cp.async.commit_group;");
        if (kc < 5) {
            stageB(kc + 1, bi ^ 1);
            asm volatile("cp.async.wait_group 1;");
        } else {
            asm volatile("cp.async.wait_group 0;");
        }
        __syncthreads();

        const __nv_bfloat16* bAh = (const __nv_bfloat16*)(smc + B16_SA_H);
        const __nv_bfloat16* bAl = (const __nv_bfloat16*)(smc + B16_SA_L);
        const __nv_bfloat16* bBh = (const __nv_bfloat16*)(smc + B16_SB + bi * B16_SET);
        const __nv_bfloat16* bBl = (const __nv_bfloat16*)(smc + B16_SB + bi * B16_SET + 17408);
#pragma unroll
        for (int k16 = 0; k16 < 4; k16++) {
            wmma::fragment<wmma::matrix_b, 16, 16, 16, __nv_bfloat16, wmma::row_major> bh[2], bl[2];
#pragma unroll
            for (int j = 0; j < 2; j++) {
                wmma::load_matrix_sync(bh[j], &bBh[(k16 * 16) * SB_STR + wn * 32 + j * 16], SB_STR);
                wmma::load_matrix_sync(bl[j], &bBl[(k16 * 16) * SB_STR + wn * 32 + j * 16], SB_STR);
            }
#pragma unroll
            for (int i = 0; i < 4; i++) {
                wmma::fragment<wmma::matrix_a, 16, 16, 16, __nv_bfloat16, wmma::row_major> ah, al;
                wmma::load_matrix_sync(ah, &bAh[(wm * 64 + i * 16) * SA_STR + k16 * 16], SA_STR);
                wmma::load_matrix_sync(al, &bAl[(wm * 64 + i * 16) * SA_STR + k16 * 16], SA_STR);
#pragma unroll
                for (int j = 0; j < 2; j++) {
                    wmma::mma_sync(acc[i][j], ah, bh[j], acc[i][j]);
                    wmma::mma_sync(acc[i][j], ah, bl[j], acc[i][j]);
                    wmma::mma_sync(acc[i][j], al, bh[j], acc[i][j]);
                }
            }
        }
        __syncthreads();
    }

    float* sC = (float*)smc;
#pragma unroll
    for (int i = 0; i < 4; i++)
#pragma unroll
        for (int j = 0; j < 2; j++)
            wmma::store_matrix_sync(&sC[(wm * 64 + i * 16) * SC_STR + wn * 32 + j * 16],
                                    acc[i][j], SC_STR, wmma::mem_row_major);
    __syncthreads();
#pragma unroll
    for (int i = 0; i < 16; i++) {
        int e = i * 512 + tid;
        int r = e >> 5, c4 = e & 31;
        float4 v = *(const float4*)&sC[r * SC_STR + c4 * 4];
        if (bias) {
            float4 bv = *(const float4*)&bias[n0 + c4 * 4];
            v.x += bv.x; v.y += bv.y; v.z += bv.z; v.w += bv.w;
        }
        *(float4*)&C[(m0 + r) * Ntot + n0 + c4 * 4] = v;
    }
}

// ============================================================================
// K2: register-tiled windowed attention, 4 heads in flight (unchanged R13)
// ============================================================================
#define HS 2308
#define SQ_OFF 0
#define SK_OFF 9232
#define SV_OFF 18464
#define PS_OFF 27696
#define ATTN_SMEM_FLOATS 45104

__global__ void __launch_bounds__(512, 1)
attn_win()
{
    extern __shared__ float sm[];
    const int tid = threadIdx.x;
    const int n = blockIdx.x;
    const int b = n >> 6, ih = (n >> 3) & 7, iw = n & 7;
    const int tb = (b * 64 + ih * 8) * 64 + iw * 8;

    const int hq = tid >> 7;
    const int st = tid & 127;
    const int rg = st >> 3;
    const int cg8 = st & 7;
    const int r0 = rg * 4;
    const int rql = st >> 2;
    const int dq = st & 3;

    for (int hp = 0; hp < 3; hp++) {
        const int h0 = hp * 4;
        __syncthreads();
#pragma unroll
        for (int i = 0; i < 12; i++) {
            int e = i * 512 + tid;
            int c8 = e & 7;
            int r = e >> 3;
            int hh4 = r & 3; r >>= 2;
            int p = r % 3;
            int t = r / 3;
            long gf4 = (long)(tb + (t >> 3) * 64 + (t & 7)) * 288 + p * 96 + (h0 + hh4) * 8 + c8;
            float4 v = ((const float4*)g_qkv)[gf4];
            int base = (p == 0) ? SQ_OFF : (p == 1 ? SK_OFF : SV_OFF);
            if (p == 0) { v.x *= SCALE; v.y *= SCALE; v.z *= SCALE; v.w *= SCALE; }
            *(float4*)&sm[base + hh4 * HS + t * 36 + c8 * 4] = v;
        }
        __syncthreads();

        float acc[4][8];
#pragma unroll
        for (int i = 0; i < 4; i++)
#pragma unroll
            for (int j = 0; j < 8; j++) acc[i][j] = 0.f;

        const float* qb = &sm[SQ_OFF + hq * HS];
        const float* kb = &sm[SK_OFF + hq * HS];
#pragma unroll
        for (int dblk = 0; dblk < 8; dblk++) {
            float4 qv[4];
#pragma unroll
            for (int i = 0; i < 4; i++)
                qv[i] = *(const float4*)&qb[(r0 + i) * 36 + dblk * 4];
#pragma unroll
            for (int j = 0; j < 8; j++) {
                float4 kv = *(const float4*)&kb[(j * 8 + cg8) * 36 + dblk * 4];
#pragma unroll
                for (int i = 0; i < 4; i++) {
                    acc[i][j] = fmaf(qv[i].x, kv.x, acc[i][j]);
                    acc[i][j] = fmaf(qv[i].y, kv.y, acc[i][j]);
                    acc[i][j] = fmaf(qv[i].z, kv.z, acc[i][j]);
                    acc[i][j] = fmaf(qv[i].w, kv.w, acc[i][j]);
                }
            }
        }

        float* psb = &sm[PS_OFF + hq * 4352];
#pragma unroll
        for (int i = 0; i < 4; i++) {
            float m = acc[i][0];
#pragma unroll
            for (int j = 1; j < 8; j++) m = fmaxf(m, acc[i][j]);
            m = fmaxf(m, __shfl_xor_sync(0xffffffffu, m, 1));
            m = fmaxf(m, __shfl_xor_sync(0xffffffffu, m, 2));
            m = fmaxf(m, __shfl_xor_sync(0xffffffffu, m, 4));
            float s = 0.f;
#pragma unroll
            for (int j = 0; j < 8; j++) { acc[i][j] = __expf(acc[i][j] - m); s += acc[i][j]; }
            s += __shfl_xor_sync(0xffffffffu, s, 1);
            s += __shfl_xor_sync(0xffffffffu, s, 2);
            s += __shfl_xor_sync(0xffffffffu, s, 4);
            float inv = 1.f / s;
#pragma unroll
            for (int j = 0; j < 8; j++)
                psb[(r0 + i) * 68 + j * 8 + cg8] = acc[i][j] * inv;
        }
        __syncthreads();

        ull oa[2][4];
#pragma unroll
        for (int i = 0; i < 2; i++)
#pragma unroll
            for (int j = 0; j < 4; j++) oa[i][j] = 0ull;

        const float* vb = &sm[SV_OFF + hq * HS + dq * 8];
        const float* p0 = &sm[PS_OFF + hq * 4352 + (rql * 2) * 68];
        const float* p1 = p0 + 68;
#pragma unroll 8
        for (int j = 0; j < 64; j++) {
            ulonglong2 va = *(const ulonglong2*)(vb + j * 36);
            ulonglong2 vc = *(const ulonglong2*)(vb + j * 36 + 4);
            ull P0 = pk2(p0[j], p0[j]);
            ull P1 = pk2(p1[j], p1[j]);
            ffma2(oa[0][0], P0, va.x); ffma2(oa[0][1], P0, va.y);
            ffma2(oa[0][2], P0, vc.x); ffma2(oa[0][3], P0, vc.y);
            ffma2(oa[1][0], P1, va.x); ffma2(oa[1][1], P1, va.y);
            ffma2(oa[1][2], P1, vc.x); ffma2(oa[1][3], P1, vc.y);
        }
#pragma unroll
        for (int i = 0; i < 2; i++) {
            int row = rql * 2 + i;
            long gtok = tb + (row >> 3) * 64 + (row & 7);
            long go = gtok * 384 + (h0 + hq) * 32 + dq * 8;
            float o[8];
            upk2(oa[i][0], o[0], o[1]); upk2(oa[i][1], o[2], o[3]);
            upk2(oa[i][2], o[4], o[5]); upk2(oa[i][3], o[6], o[7]);
            uint32_t hw[4], lw[4];
#pragma unroll
            for (int q2 = 0; q2 < 4; q2++) {
                __nv_bfloat162 h2 = __floats2bfloat162_rn(o[2 * q2], o[2 * q2 + 1]);
                __nv_bfloat162 l2 = __floats2bfloat162_rn(o[2 * q2] - __low2float(h2),
                                                          o[2 * q2 + 1] - __high2float(h2));
                hw[q2] = *(uint32_t*)&h2;
                lw[q2] = *(uint32_t*)&l2;
            }
            *(uint4*)&g_aoh[go] = make_uint4(hw[0], hw[1], hw[2], hw[3]);
            *(uint4*)&g_aol[go] = make_uint4(lw[0], lw[1], lw[2], lw[3]);
        }
    }
}

// ============================================================================
extern "C" void kernel_launch(void* const* d_in, const int* in_sizes, int n_in,
                              void* d_out, int out_size)
{
    const float* x    = (const float*)d_in[0];
    const float* wqkv = (const float*)d_in[1];
    const float* wout = (const float*)d_in[2];
    const float* bout = (const float*)d_in[3];
    float* out = (float*)d_out;

    static float* p_qkv = nullptr;
    static __nv_bfloat16 *p_aoh, *p_aol, *p_wqh, *p_woh, *p_wol;
    if (!p_qkv) {
        cudaGetSymbolAddress((void**)&p_qkv, g_qkv);
        cudaGetSymbolAddress((void**)&p_aoh, g_aoh);
        cudaGetSymbolAddress((void**)&p_aol, g_aol);
        cudaGetSymbolAddress((void**)&p_wqh, g_wqh);
        cudaGetSymbolAddress((void**)&p_woh, g_woh);
        cudaGetSymbolAddress((void**)&p_wol, g_wol);
        cudaFuncSetAttribute(gemm_f16_2m,
                             cudaFuncAttributeMaxDynamicSharedMemorySize, F16_SMEM);
        cudaFuncSetAttribute(gemm_bf16,
                             cudaFuncAttributeMaxDynamicSharedMemorySize, B16_SMEM);
        cudaFuncSetAttribute(attn_win,
                             cudaFuncAttributeMaxDynamicSharedMemorySize,
                             ATTN_SMEM_FLOATS * sizeof(float));
    }

    // x -> fp16 hi/lo (exact split) into g_aoh/g_aol; wqkv -> fp16 single
    conv_f16_hilo<<<12582912 / 256, 256>>>(x, (__half*)p_aoh, (__half*)p_aol, 12582912);
    conv_f16<<<110592 / 256, 256>>>(wqkv, (__half*)p_wqh, 110592);
    conv_hilo<<<36864 / 256, 256>>>(wout, p_woh, p_wol, 36864);

    dim3 g1(512, 9), g3(512, 3);
    gemm_f16_2m<<<g1, 512, F16_SMEM>>>((const __half*)p_aoh, (const __half*)p_aol,
                                       (const __half*)p_wqh, p_qkv, 1152);
    attn_win<<<2048, 512, ATTN_SMEM_FLOATS * sizeof(float)>>>();
    gemm_bf16<<<g3, 512, B16_SMEM>>>(p_aoh, p_aol, p_woh, p_wol, bout, out, 384);
}